// round 12
// baseline (speedup 1.0000x reference)
#include <cuda_runtime.h>
#include <cuda_bf16.h>
#include <stdint.h>

#define H      128
#define NC_MAX 100000
#define NU_MAX 100000
#define E_MAX  1600000

// Scratch: __device__ globals (allocation-free rule)
__device__ __align__(16) float g_hu[(size_t)NU_MAX * H];
__device__ __align__(16) float g_hc[(size_t)NC_MAX * H];
__device__ __align__(16) float g_mean[(size_t)NC_MAX * H];
__device__ int g_deg[NC_MAX];
__device__ int g_off[NC_MAX];
__device__ int g_cursor[NC_MAX];
__device__ int g_csr[E_MAX];
__device__ int g_bsum[512];

// ============================= PTX helpers (portable) =======================
__device__ __forceinline__ uint32_t smem_u32(const void* p) {
    uint32_t a;
    asm("{ .reg .u64 t; cvta.to.shared.u64 t, %1; cvt.u32.u64 %0, t; }"
        : "=r"(a) : "l"(p));
    return a;
}
__device__ __forceinline__ void ldsm_x4(uint32_t* r, uint32_t addr) {
    asm volatile("ldmatrix.sync.aligned.m8n8.x4.shared.b16 {%0,%1,%2,%3}, [%4];"
                 : "=r"(r[0]), "=r"(r[1]), "=r"(r[2]), "=r"(r[3]) : "r"(addr));
}
__device__ __forceinline__ void ldsm_x4_t(uint32_t* r, uint32_t addr) {
    asm volatile("ldmatrix.sync.aligned.m8n8.x4.trans.shared.b16 {%0,%1,%2,%3}, [%4];"
                 : "=r"(r[0]), "=r"(r[1]), "=r"(r[2]), "=r"(r[3]) : "r"(addr));
}
__device__ __forceinline__ void mma_bf16(float* d, const uint32_t* a,
                                         uint32_t b0, uint32_t b1) {
    asm volatile(
        "mma.sync.aligned.m16n8k16.row.col.f32.bf16.bf16.f32 "
        "{%0,%1,%2,%3}, {%4,%5,%6,%7}, {%8,%9}, {%0,%1,%2,%3};"
        : "+f"(d[0]), "+f"(d[1]), "+f"(d[2]), "+f"(d[3])
        : "r"(a[0]), "r"(a[1]), "r"(a[2]), "r"(a[3]), "r"(b0), "r"(b1));
}

// fp32 -> (bf16 hi, bf16 lo), packed
__device__ __forceinline__ void cvt_hl4(float4 v, uint2& hv, uint2& lv) {
    float f[4] = {v.x, v.y, v.z, v.w};
    uint32_t h[4], l[4];
#pragma unroll
    for (int j = 0; j < 4; j++) {
        __nv_bfloat16 hb = __float2bfloat16_rn(f[j]);
        float hf = __bfloat162float(hb);
        __nv_bfloat16 lb = __float2bfloat16_rn(f[j] - hf);
        h[j] = (uint32_t)__bfloat16_as_ushort(hb);
        l[j] = (uint32_t)__bfloat16_as_ushort(lb);
    }
    hv = make_uint2(h[0] | (h[1] << 16), h[2] | (h[3] << 16));
    lv = make_uint2(l[0] | (l[1] << 16), l[2] | (l[3] << 16));
}
__device__ __forceinline__ void cvt_hl2(float a, float b, uint32_t& hv, uint32_t& lv) {
    __nv_bfloat16 h0 = __float2bfloat16_rn(a), h1 = __float2bfloat16_rn(b);
    float f0 = __bfloat162float(h0), f1 = __bfloat162float(h1);
    __nv_bfloat16 l0 = __float2bfloat16_rn(a - f0), l1 = __float2bfloat16_rn(b - f1);
    hv = (uint32_t)__bfloat16_as_ushort(h0) |
         ((uint32_t)__bfloat16_as_ushort(h1) << 16);
    lv = (uint32_t)__bfloat16_as_ushort(l0) |
         ((uint32_t)__bfloat16_as_ushort(l1) << 16);
}

// ============================================================================
// Projection (2 CTAs/SM): relu(X @ W + b) -> dst. CTA tile 64 rows x 64 cols
// (colhalf selects output cols). 8 warps as 4x2; warp tile 16x32.
// Single A buffer + LDG-prefetch-into-regs. smem: K=256 -> 108,544 B.
// ============================================================================
template <int KTOT>
__device__ void run_proj(const float* __restrict__ X, const float* __restrict__ W,
                         const float* __restrict__ bias, float* __restrict__ dst,
                         int N, int colhalf, int bid, int nb, char* smc) {
    constexpr int NCHUNK = KTOT / 128;
    constexpr int PITCH = 136;   // A row pitch (bf16 elems)
    constexpr int BPITCH = 72;   // B row pitch (bf16 elems), 144B
    __nv_bfloat16* Bh = reinterpret_cast<__nv_bfloat16*>(smc);
    __nv_bfloat16* Bl = Bh + KTOT * BPITCH;
    __nv_bfloat16* Ah = Bl + KTOT * BPITCH;
    __nv_bfloat16* Al = Ah + 64 * PITCH;

    const int t = threadIdx.x;
    const int wid = t >> 5, lane = t & 31;
    const int wm = wid >> 1, wn = wid & 1;

    // Stage this CTA's 64-col slice of W (hi/lo)
    for (int i = t; i < KTOT * 16; i += 256) {
        int k = i >> 4, n4 = (i & 15) * 4;
        float4 w = *reinterpret_cast<const float4*>(W + (size_t)k * 128 +
                                                    colhalf * 64 + n4);
        uint2 hv, lv;
        cvt_hl4(w, hv, lv);
        *reinterpret_cast<uint2*>(Bh + k * BPITCH + n4) = hv;
        *reinterpret_cast<uint2*>(Bl + k * BPITCH + n4) = lv;
    }

    const uint32_t ah_u = smem_u32(Ah), al_u = smem_u32(Al);
    const uint32_t bh_u = smem_u32(Bh), bl_u = smem_u32(Bl);
    const int a_row_l = lane & 15, a_col_l = (lane >> 4) * 8;
    const int b_k_l = (lane & 7) + ((lane >> 3) & 1) * 8;
    const int b_n_l = (lane >> 4) * 8;

    float2 bv[4];
#pragma unroll
    for (int n8 = 0; n8 < 4; n8++)
        bv[n8] = *reinterpret_cast<const float2*>(bias + colhalf * 64 + wn * 32 +
                                                  n8 * 8 + (lane & 3) * 2);

    const int ntiles = (N + 63) >> 6;
    const int nloc = (ntiles > bid) ? (ntiles - 1 - bid) / nb + 1 : 0;
    const int total = nloc * NCHUNK;

    float4 vv[8];
    auto ldg_chunk = [&](int g) {
        const int tile = bid + (g / NCHUNK) * nb;
        const int c = g % NCHUNK;
        const int row0 = tile << 6;
#pragma unroll
        for (int it = 0; it < 8; it++) {
            int i = t + it * 256;
            int rr = row0 + (i >> 5), c4 = (i & 31) * 4;
            vv[it] = (rr < N) ? *reinterpret_cast<const float4*>(
                                    X + (size_t)rr * KTOT + c * 128 + c4)
                              : make_float4(0.f, 0.f, 0.f, 0.f);
        }
    };

    float acc[4][4];
#pragma unroll
    for (int n8 = 0; n8 < 4; n8++)
#pragma unroll
        for (int e = 0; e < 4; e++) acc[n8][e] = 0.f;

    if (total > 0) ldg_chunk(0);

    for (int g = 0; g < total; g++) {
        const int tile = bid + (g / NCHUNK) * nb;
        const int c = g % NCHUNK;

        if (g > 0) __syncthreads();  // prev MMA done reading A buffer
        // Convert vv (chunk g) -> A buffer
#pragma unroll
        for (int it = 0; it < 8; it++) {
            int i = t + it * 256;
            int r = i >> 5, c4 = (i & 31) * 4;
            uint2 hv, lv;
            cvt_hl4(vv[it], hv, lv);
            *reinterpret_cast<uint2*>(Ah + r * PITCH + c4) = hv;
            *reinterpret_cast<uint2*>(Al + r * PITCH + c4) = lv;
        }
        __syncthreads();
        if (g + 1 < total) ldg_chunk(g + 1);  // prefetch next (regs only)

        // ---- MMA over this 128-wide K chunk ----
#pragma unroll 1
        for (int k0 = 0; k0 < 128; k0 += 16) {
            uint32_t afh[4], afl[4];
            uint32_t aoff = (uint32_t)((wm * 16 + a_row_l) * PITCH + k0 + a_col_l) * 2;
            ldsm_x4(afh, ah_u + aoff);
            ldsm_x4(afl, al_u + aoff);
            uint32_t bfh[2][4], bfl[2][4];
#pragma unroll
            for (int ng = 0; ng < 2; ng++) {
                uint32_t boff = (uint32_t)((c * 128 + k0 + b_k_l) * BPITCH +
                                           wn * 32 + ng * 16 + b_n_l) * 2;
                ldsm_x4_t(bfh[ng], bh_u + boff);
                ldsm_x4_t(bfl[ng], bl_u + boff);
            }
#pragma unroll
            for (int n8 = 0; n8 < 4; n8++) {
                int ng = n8 >> 1, sb = (n8 & 1) * 2;
                mma_bf16(acc[n8], afh, bfh[ng][sb], bfh[ng][sb + 1]);
                mma_bf16(acc[n8], afh, bfl[ng][sb], bfl[ng][sb + 1]);
                mma_bf16(acc[n8], afl, bfh[ng][sb], bfh[ng][sb + 1]);
            }
        }

        // ---- Epilogue on last chunk of the tile ----
        if (c == NCHUNK - 1) {
            const int row0 = tile << 6;
            int r0w = row0 + wm * 16 + (lane >> 2);
#pragma unroll
            for (int n8 = 0; n8 < 4; n8++) {
                int col = colhalf * 64 + wn * 32 + n8 * 8 + (lane & 3) * 2;
                float2 o0, o1;
                o0.x = fmaxf(acc[n8][0] + bv[n8].x, 0.f);
                o0.y = fmaxf(acc[n8][1] + bv[n8].y, 0.f);
                o1.x = fmaxf(acc[n8][2] + bv[n8].x, 0.f);
                o1.y = fmaxf(acc[n8][3] + bv[n8].y, 0.f);
                if (r0w < N)
                    *reinterpret_cast<float2*>(dst + (size_t)r0w * 128 + col) = o0;
                if (r0w + 8 < N)
                    *reinterpret_cast<float2*>(dst + (size_t)(r0w + 8) * 128 + col) = o1;
            }
#pragma unroll
            for (int n8 = 0; n8 < 4; n8++)
#pragma unroll
                for (int e = 0; e < 4; e++) acc[n8][e] = 0.f;
        }
    }
}

// Fused projections, 304 CTAs (2/SM):
// bid 0-101: user (K=128), colhalf=bid&1, row tiles strided 51
// bid 102-303: content (K=256), colhalf=(bid-102)&1, strided 101
__global__ void __launch_bounds__(256, 2)
proj_fused(const float* __restrict__ xc, const float* __restrict__ xu,
           const float* __restrict__ Wc, const float* __restrict__ bc,
           const float* __restrict__ Wu, const float* __restrict__ bu,
           int Nc, int Nu) {
    extern __shared__ char smc[];
    if (blockIdx.x < 102) {
        int b = blockIdx.x;
        run_proj<128>(xu, Wu, bu, g_hu, Nu, b & 1, b >> 1, 51, smc);
    } else {
        int b = blockIdx.x - 102;
        run_proj<256>(xc, Wc, bc, g_hc, Nc, b & 1, b >> 1, 101, smc);
    }
}

// ============================================================================
// Combine + output fused (round-7 version, unchanged from 334us best).
// ============================================================================
__global__ void __launch_bounds__(256, 1)
combine_kernel(const float* __restrict__ Wl, const float* __restrict__ bl,
               const float* __restrict__ Wr, const float* __restrict__ Wo,
               const float* __restrict__ bo, float* __restrict__ out, int N) {
    constexpr int PITCH = 136, OPITCH = 72;
    extern __shared__ char smc[];
    __nv_bfloat16* Bh = reinterpret_cast<__nv_bfloat16*>(smc);
    __nv_bfloat16* Bl_ = Bh + 256 * PITCH;
    __nv_bfloat16* Ah = Bl_ + 256 * PITCH;
    __nv_bfloat16* Al = Ah + 64 * PITCH;
    __nv_bfloat16* Oh = Al + 64 * PITCH;
    __nv_bfloat16* Ol = Oh + 128 * OPITCH;

    const int t = threadIdx.x;
    const int wid = t >> 5, lane = t & 31;
    const int wm = wid >> 1, wn = wid & 1;

    for (int i = t; i < 256 * 32; i += 256) {
        int k = i >> 5, n4 = (i & 31) * 4;
        const float* wsrc = (k < 128) ? Wl + (size_t)k * 128
                                      : Wr + (size_t)(k - 128) * 128;
        float4 w = *reinterpret_cast<const float4*>(wsrc + n4);
        uint2 hv, lv;
        cvt_hl4(w, hv, lv);
        *reinterpret_cast<uint2*>(Bh + k * PITCH + n4) = hv;
        *reinterpret_cast<uint2*>(Bl_ + k * PITCH + n4) = lv;
    }
    for (int i = t; i < 128 * 16; i += 256) {
        int k = i >> 4, n4 = (i & 15) * 4;
        float4 w = *reinterpret_cast<const float4*>(Wo + (size_t)k * 64 + n4);
        uint2 hv, lv;
        cvt_hl4(w, hv, lv);
        *reinterpret_cast<uint2*>(Oh + k * OPITCH + n4) = hv;
        *reinterpret_cast<uint2*>(Ol + k * OPITCH + n4) = lv;
    }

    const uint32_t ah_u = smem_u32(Ah), al_u = smem_u32(Al);
    const uint32_t bh_u = smem_u32(Bh), bl_u = smem_u32(Bl_);
    const uint32_t oh_u = smem_u32(Oh), ol_u = smem_u32(Ol);
    const int a_row_l = lane & 15, a_col_l = (lane >> 4) * 8;
    const int b_k_l = (lane & 7) + ((lane >> 3) & 1) * 8;
    const int b_n_l = (lane >> 4) * 8;

    float2 blv[8];
#pragma unroll
    for (int n8 = 0; n8 < 8; n8++)
        blv[n8] = *reinterpret_cast<const float2*>(bl + wn * 64 + n8 * 8 +
                                                   (lane & 3) * 2);
    float2 bov[4];
#pragma unroll
    for (int n8 = 0; n8 < 4; n8++)
        bov[n8] = *reinterpret_cast<const float2*>(bo + wn * 32 + n8 * 8 +
                                                   (lane & 3) * 2);

    const int ntiles = (N + 63) >> 6;
    for (int tile = blockIdx.x; tile < ntiles; tile += gridDim.x) {
        const int row0 = tile << 6;
        float acc[8][4];
#pragma unroll
        for (int n8 = 0; n8 < 8; n8++)
#pragma unroll
            for (int e = 0; e < 4; e++) acc[n8][e] = 0.f;

        for (int c = 0; c < 2; ++c) {
            __syncthreads();
            const float* src = (c == 0) ? g_mean : g_hc;
            float4 vv[8];
#pragma unroll
            for (int it = 0; it < 8; it++) {
                int i = t + it * 256;
                int rr = row0 + (i >> 5), c4 = (i & 31) * 4;
                vv[it] = (rr < N) ? *reinterpret_cast<const float4*>(
                                        src + (size_t)rr * 128 + c4)
                                  : make_float4(0.f, 0.f, 0.f, 0.f);
            }
#pragma unroll
            for (int it = 0; it < 8; it++) {
                int i = t + it * 256;
                int r = i >> 5, c4 = (i & 31) * 4;
                uint2 hv, lv;
                cvt_hl4(vv[it], hv, lv);
                *reinterpret_cast<uint2*>(Ah + r * PITCH + c4) = hv;
                *reinterpret_cast<uint2*>(Al + r * PITCH + c4) = lv;
            }
            __syncthreads();
#pragma unroll 1
            for (int k0 = 0; k0 < 128; k0 += 16) {
                uint32_t afh[4], afl[4];
                uint32_t aoff = (uint32_t)((wm * 16 + a_row_l) * PITCH + k0 + a_col_l) * 2;
                ldsm_x4(afh, ah_u + aoff);
                ldsm_x4(afl, al_u + aoff);
                uint32_t bfh[4][4], bfl[4][4];
#pragma unroll
                for (int ng = 0; ng < 4; ng++) {
                    uint32_t boff = (uint32_t)((c * 128 + k0 + b_k_l) * PITCH +
                                               wn * 64 + ng * 16 + b_n_l) * 2;
                    ldsm_x4_t(bfh[ng], bh_u + boff);
                    ldsm_x4_t(bfl[ng], bl_u + boff);
                }
#pragma unroll
                for (int n8 = 0; n8 < 8; n8++) {
                    int ng = n8 >> 1, sb = (n8 & 1) * 2;
                    mma_bf16(acc[n8], afh, bfh[ng][sb], bfh[ng][sb + 1]);
                    mma_bf16(acc[n8], afh, bfl[ng][sb], bfl[ng][sb + 1]);
                    mma_bf16(acc[n8], afl, bfh[ng][sb], bfh[ng][sb + 1]);
                }
            }
        }
        __syncthreads();

        {
            int r1 = wm * 16 + (lane >> 2);
#pragma unroll
            for (int n8 = 0; n8 < 8; n8++) {
                int col = wn * 64 + n8 * 8 + (lane & 3) * 2;
                uint32_t hv, lv;
                cvt_hl2(acc[n8][0] + blv[n8].x, acc[n8][1] + blv[n8].y, hv, lv);
                *reinterpret_cast<uint32_t*>(Ah + r1 * PITCH + col) = hv;
                *reinterpret_cast<uint32_t*>(Al + r1 * PITCH + col) = lv;
                cvt_hl2(acc[n8][2] + blv[n8].x, acc[n8][3] + blv[n8].y, hv, lv);
                *reinterpret_cast<uint32_t*>(Ah + (r1 + 8) * PITCH + col) = hv;
                *reinterpret_cast<uint32_t*>(Al + (r1 + 8) * PITCH + col) = lv;
            }
        }
        __syncthreads();

        float acc2[4][4];
#pragma unroll
        for (int n8 = 0; n8 < 4; n8++)
#pragma unroll
            for (int e = 0; e < 4; e++) acc2[n8][e] = 0.f;
#pragma unroll 1
        for (int k0 = 0; k0 < 128; k0 += 16) {
            uint32_t afh[4], afl[4];
            uint32_t aoff = (uint32_t)((wm * 16 + a_row_l) * PITCH + k0 + a_col_l) * 2;
            ldsm_x4(afh, ah_u + aoff);
            ldsm_x4(afl, al_u + aoff);
            uint32_t bfh[2][4], bfl[2][4];
#pragma unroll
            for (int ng = 0; ng < 2; ng++) {
                uint32_t boff = (uint32_t)((k0 + b_k_l) * OPITCH +
                                           wn * 32 + ng * 16 + b_n_l) * 2;
                ldsm_x4_t(bfh[ng], oh_u + boff);
                ldsm_x4_t(bfl[ng], ol_u + boff);
            }
#pragma unroll
            for (int n8 = 0; n8 < 4; n8++) {
                int ng = n8 >> 1, sb = (n8 & 1) * 2;
                mma_bf16(acc2[n8], afh, bfh[ng][sb], bfh[ng][sb + 1]);
                mma_bf16(acc2[n8], afh, bfl[ng][sb], bfl[ng][sb + 1]);
                mma_bf16(acc2[n8], afl, bfh[ng][sb], bfh[ng][sb + 1]);
            }
        }
        int r0w = row0 + wm * 16 + (lane >> 2);
#pragma unroll
        for (int n8 = 0; n8 < 4; n8++) {
            int col = wn * 32 + n8 * 8 + (lane & 3) * 2;
            float2 o0, o1;
            o0.x = acc2[n8][0] + bov[n8].x;
            o0.y = acc2[n8][1] + bov[n8].y;
            o1.x = acc2[n8][2] + bov[n8].x;
            o1.y = acc2[n8][3] + bov[n8].y;
            if (r0w < N)
                *reinterpret_cast<float2*>(out + (size_t)r0w * 64 + col) = o0;
            if (r0w + 8 < N)
                *reinterpret_cast<float2*>(out + (size_t)(r0w + 8) * 64 + col) = o1;
        }
    }
}

// ============================ CSR build =====================================
__global__ void zero_deg_kernel(int nc) {
    int i = blockIdx.x * blockDim.x + threadIdx.x;
    int stride = gridDim.x * blockDim.x;
    for (; i < nc; i += stride) g_deg[i] = 0;
}
__global__ void hist_kernel(const int* __restrict__ ei, int E) {
    int i = blockIdx.x * blockDim.x + threadIdx.x;
    if (i < E) atomicAdd(&g_deg[ei[E + i]], 1);
}
__global__ void scan1_kernel(int nc) {
    __shared__ int s[256];
    int t = threadIdx.x;
    int i = blockIdx.x * 256 + t;
    s[t] = (i < nc) ? g_deg[i] : 0;
    __syncthreads();
    for (int d = 128; d > 0; d >>= 1) {
        if (t < d) s[t] += s[t + d];
        __syncthreads();
    }
    if (t == 0) g_bsum[blockIdx.x] = s[0];
}
__global__ void scan2_kernel(int nb) {
    __shared__ int s[512];
    int t = threadIdx.x;
    int v = (t < nb) ? g_bsum[t] : 0;
    s[t] = v;
    __syncthreads();
    for (int d = 1; d < 512; d <<= 1) {
        int add = (t >= d) ? s[t - d] : 0;
        __syncthreads();
        s[t] += add;
        __syncthreads();
    }
    if (t < nb) g_bsum[t] = s[t] - v;
}
__global__ void scan3_kernel(int nc) {
    __shared__ int s[256];
    int t = threadIdx.x;
    int i = blockIdx.x * 256 + t;
    int v = (i < nc) ? g_deg[i] : 0;
    s[t] = v;
    __syncthreads();
    for (int d = 1; d < 256; d <<= 1) {
        int add = (t >= d) ? s[t - d] : 0;
        __syncthreads();
        s[t] += add;
        __syncthreads();
    }
    if (i < nc) {
        int off = g_bsum[blockIdx.x] + s[t] - v;
        g_off[i] = off;
        g_cursor[i] = off;
    }
}
__global__ void fill_kernel(const int* __restrict__ ei, int E) {
    int i = blockIdx.x * blockDim.x + threadIdx.x;
    if (i < E) {
        int dst = ei[E + i];
        int pos = atomicAdd(&g_cursor[dst], 1);
        g_csr[pos] = ei[i];
    }
}

// ------------------- Gather-mean: warp per content node --------------------
__global__ void agg_kernel(int nc) {
    const int warp = (blockIdx.x * blockDim.x + threadIdx.x) >> 5;
    const int lane = threadIdx.x & 31;
    if (warp >= nc) return;
    const int s0 = g_off[warp];
    const int d = g_deg[warp];
    float4 acc = make_float4(0.f, 0.f, 0.f, 0.f);
    for (int base = 0; base < d; base += 32) {
        int my = (base + lane < d) ? g_csr[s0 + base + lane] : 0;
        int lim = min(32, d - base);
        for (int j = 0; j < lim; j++) {
            int nbr = __shfl_sync(0xffffffffu, my, j);
            float4 v = reinterpret_cast<const float4*>(g_hu + (size_t)nbr * H)[lane];
            acc.x += v.x; acc.y += v.y; acc.z += v.z; acc.w += v.w;
        }
    }
    float inv = 1.f / fmaxf((float)d, 1.f);
    acc.x *= inv; acc.y *= inv; acc.z *= inv; acc.w *= inv;
    reinterpret_cast<float4*>(g_mean + (size_t)warp * H)[lane] = acc;
}

// ---------------------------------------------------------------------------
extern "C" void kernel_launch(void* const* d_in, const int* in_sizes, int n_in,
                              void* d_out, int out_size) {
    const float* x_content = (const float*)d_in[0];
    const float* x_user    = (const float*)d_in[1];
    const int*   ei        = (const int*)d_in[2];   // int32 (JAX x64 off)
    const float* Wc = (const float*)d_in[3];
    const float* bc = (const float*)d_in[4];
    const float* Wu = (const float*)d_in[5];
    const float* bu = (const float*)d_in[6];
    const float* Wl = (const float*)d_in[7];
    const float* bl = (const float*)d_in[8];
    const float* Wr = (const float*)d_in[9];
    const float* Wo = (const float*)d_in[10];
    const float* bo = (const float*)d_in[11];
    float* out = (float*)d_out;

    const int Nc = in_sizes[0] / 256;
    const int Nu = in_sizes[1] / 128;
    const int E  = in_sizes[2] / 2;

    // proj (content path): B 2*256*72*2 + A 2*64*136*2 = 108544 -> 2 CTAs/SM
    const int smem_proj = (2 * 256 * 72 + 2 * 64 * 136) * 2;
    // combine (round 7): 210944
    const int smem_comb = (2 * 256 * 136 + 2 * 64 * 136 + 2 * 128 * 72) * 2;

    cudaFuncSetAttribute(proj_fused,
                         cudaFuncAttributeMaxDynamicSharedMemorySize, smem_proj);
    cudaFuncSetAttribute(combine_kernel,
                         cudaFuncAttributeMaxDynamicSharedMemorySize, smem_comb);

    const int nb = (Nc + 255) / 256;  // <= 512

    zero_deg_kernel<<<256, 256>>>(Nc);
    hist_kernel<<<(E + 255) / 256, 256>>>(ei, E);
    scan1_kernel<<<nb, 256>>>(Nc);
    proj_fused<<<304, 256, smem_proj>>>(x_content, x_user, Wc, bc, Wu, bu, Nc, Nu);
    scan2_kernel<<<1, 512>>>(nb);
    scan3_kernel<<<nb, 256>>>(Nc);
    fill_kernel<<<(E + 255) / 256, 256>>>(ei, E);
    agg_kernel<<<(Nc * 32 + 255) / 256, 256>>>(Nc);
    combine_kernel<<<152, 256, smem_comb>>>(Wl, bl, Wr, Wo, bo, out, Nc);
}

// round 13
// speedup vs baseline: 1.0225x; 1.0225x over previous
#include <cuda_runtime.h>
#include <cuda_bf16.h>
#include <stdint.h>

#define H      128
#define NC_MAX 100000
#define NU_MAX 100000
#define E_MAX  1600000

// Scratch: __device__ globals (allocation-free rule)
__device__ __align__(16) float g_hu[(size_t)NU_MAX * H];
__device__ __align__(16) float g_hc[(size_t)NC_MAX * H];
__device__ __align__(16) float g_mean[(size_t)NC_MAX * H];
__device__ int g_deg[NC_MAX];
__device__ int g_off[NC_MAX];
__device__ int g_cursor[NC_MAX];
__device__ int g_csr[E_MAX];
__device__ int g_bsum[512];

// ============================= PTX helpers (portable) =======================
__device__ __forceinline__ uint32_t smem_u32(const void* p) {
    uint32_t a;
    asm("{ .reg .u64 t; cvta.to.shared.u64 t, %1; cvt.u32.u64 %0, t; }"
        : "=r"(a) : "l"(p));
    return a;
}
__device__ __forceinline__ void ldsm_x4(uint32_t* r, uint32_t addr) {
    asm volatile("ldmatrix.sync.aligned.m8n8.x4.shared.b16 {%0,%1,%2,%3}, [%4];"
                 : "=r"(r[0]), "=r"(r[1]), "=r"(r[2]), "=r"(r[3]) : "r"(addr));
}
__device__ __forceinline__ void ldsm_x4_t(uint32_t* r, uint32_t addr) {
    asm volatile("ldmatrix.sync.aligned.m8n8.x4.trans.shared.b16 {%0,%1,%2,%3}, [%4];"
                 : "=r"(r[0]), "=r"(r[1]), "=r"(r[2]), "=r"(r[3]) : "r"(addr));
}
__device__ __forceinline__ void mma_bf16(float* d, const uint32_t* a,
                                         uint32_t b0, uint32_t b1) {
    asm volatile(
        "mma.sync.aligned.m16n8k16.row.col.f32.bf16.bf16.f32 "
        "{%0,%1,%2,%3}, {%4,%5,%6,%7}, {%8,%9}, {%0,%1,%2,%3};"
        : "+f"(d[0]), "+f"(d[1]), "+f"(d[2]), "+f"(d[3])
        : "r"(a[0]), "r"(a[1]), "r"(a[2]), "r"(a[3]), "r"(b0), "r"(b1));
}

// fp32 -> (bf16 hi, bf16 lo), packed
__device__ __forceinline__ void cvt_hl4(float4 v, uint2& hv, uint2& lv) {
    float f[4] = {v.x, v.y, v.z, v.w};
    uint32_t h[4], l[4];
#pragma unroll
    for (int j = 0; j < 4; j++) {
        __nv_bfloat16 hb = __float2bfloat16_rn(f[j]);
        float hf = __bfloat162float(hb);
        __nv_bfloat16 lb = __float2bfloat16_rn(f[j] - hf);
        h[j] = (uint32_t)__bfloat16_as_ushort(hb);
        l[j] = (uint32_t)__bfloat16_as_ushort(lb);
    }
    hv = make_uint2(h[0] | (h[1] << 16), h[2] | (h[3] << 16));
    lv = make_uint2(l[0] | (l[1] << 16), l[2] | (l[3] << 16));
}
__device__ __forceinline__ void cvt_hl2(float a, float b, uint32_t& hv, uint32_t& lv) {
    __nv_bfloat16 h0 = __float2bfloat16_rn(a), h1 = __float2bfloat16_rn(b);
    float f0 = __bfloat162float(h0), f1 = __bfloat162float(h1);
    __nv_bfloat16 l0 = __float2bfloat16_rn(a - f0), l1 = __float2bfloat16_rn(b - f1);
    hv = (uint32_t)__bfloat16_as_ushort(h0) |
         ((uint32_t)__bfloat16_as_ushort(h1) << 16);
    lv = (uint32_t)__bfloat16_as_ushort(l0) |
         ((uint32_t)__bfloat16_as_ushort(l1) << 16);
}

// ============================================================================
// Projection (512 threads, 16 warps/SM): relu(X @ W + b) -> dst.
// CTA tile 128 rows x 128 cols; warp grid 4x4; warp tile 32x32.
// Single A buffer (hi/lo); staging in 2 sequential 4-float4 batches.
// smem (K=256): B 139,264 + A 69,632 = 208,896 B (1 CTA/SM, 16 warps).
// ============================================================================
template <int KTOT>
__device__ void run_proj(const float* __restrict__ X, const float* __restrict__ W,
                         const float* __restrict__ bias, float* __restrict__ dst,
                         int N, int bid, int nb, char* smc) {
    constexpr int NCHUNK = KTOT / 128;
    constexpr int PITCH = 136;
    __nv_bfloat16* Bh = reinterpret_cast<__nv_bfloat16*>(smc);
    __nv_bfloat16* Bl = Bh + KTOT * PITCH;
    __nv_bfloat16* Ah = Bl + KTOT * PITCH;
    __nv_bfloat16* Al = Ah + 128 * PITCH;

    const int t = threadIdx.x;
    const int wid = t >> 5, lane = t & 31;
    const int wm = wid >> 2, wn = wid & 3;   // 4x4 warp grid

    // Stage weights hi/lo (full 128 cols)
    for (int i = t; i < KTOT * 32; i += 512) {
        int k = i >> 5, n4 = (i & 31) * 4;
        float4 w = *reinterpret_cast<const float4*>(W + (size_t)k * 128 + n4);
        uint2 hv, lv;
        cvt_hl4(w, hv, lv);
        *reinterpret_cast<uint2*>(Bh + k * PITCH + n4) = hv;
        *reinterpret_cast<uint2*>(Bl + k * PITCH + n4) = lv;
    }

    const uint32_t ah_u = smem_u32(Ah), al_u = smem_u32(Al);
    const uint32_t bh_u = smem_u32(Bh), bl_u = smem_u32(Bl);
    const int a_row_l = lane & 15, a_col_l = (lane >> 4) * 8;
    const int b_k_l = (lane & 7) + ((lane >> 3) & 1) * 8;
    const int b_n_l = (lane >> 4) * 8;

    float2 bv[4];
#pragma unroll
    for (int n8 = 0; n8 < 4; n8++)
        bv[n8] = *reinterpret_cast<const float2*>(bias + wn * 32 + n8 * 8 +
                                                  (lane & 3) * 2);

    const int ntiles = (N + 127) >> 7;
    const int nloc = (ntiles > bid) ? (ntiles - 1 - bid) / nb + 1 : 0;
    const int total = nloc * NCHUNK;

    float acc[2][4][4];
#pragma unroll
    for (int mt = 0; mt < 2; mt++)
#pragma unroll
        for (int n8 = 0; n8 < 4; n8++)
#pragma unroll
            for (int e = 0; e < 4; e++) acc[mt][n8][e] = 0.f;

    for (int g = 0; g < total; g++) {
        const int tile = bid + (g / NCHUNK) * nb;
        const int c = g % NCHUNK;
        const int row0 = tile << 7;

        if (g > 0) __syncthreads();  // prev MMA done reading A buffer
        // Stage A chunk: 128x128 fp32 -> bf16 hi/lo; 2 batches of 4 float4
#pragma unroll 1
        for (int half = 0; half < 2; half++) {
            float4 vv[4];
#pragma unroll
            for (int it = 0; it < 4; it++) {
                int i = t + (half * 4 + it) * 512;
                int rr = row0 + (i >> 5), c4 = (i & 31) * 4;
                vv[it] = (rr < N) ? *reinterpret_cast<const float4*>(
                                        X + (size_t)rr * KTOT + c * 128 + c4)
                                  : make_float4(0.f, 0.f, 0.f, 0.f);
            }
#pragma unroll
            for (int it = 0; it < 4; it++) {
                int i = t + (half * 4 + it) * 512;
                int r = i >> 5, c4 = (i & 31) * 4;
                uint2 hv, lv;
                cvt_hl4(vv[it], hv, lv);
                *reinterpret_cast<uint2*>(Ah + r * PITCH + c4) = hv;
                *reinterpret_cast<uint2*>(Al + r * PITCH + c4) = lv;
            }
        }
        __syncthreads();

        // ---- MMA over this 128-wide K chunk ----
#pragma unroll 1
        for (int k0 = 0; k0 < 128; k0 += 16) {
            uint32_t afh[2][4], afl[2][4];
#pragma unroll
            for (int mt = 0; mt < 2; mt++) {
                uint32_t aoff =
                    (uint32_t)((wm * 32 + mt * 16 + a_row_l) * PITCH +
                               k0 + a_col_l) * 2;
                ldsm_x4(afh[mt], ah_u + aoff);
                ldsm_x4(afl[mt], al_u + aoff);
            }
            uint32_t bfh[2][4], bfl[2][4];
#pragma unroll
            for (int ng = 0; ng < 2; ng++) {
                uint32_t boff = (uint32_t)((c * 128 + k0 + b_k_l) * PITCH +
                                           wn * 32 + ng * 16 + b_n_l) * 2;
                ldsm_x4_t(bfh[ng], bh_u + boff);
                ldsm_x4_t(bfl[ng], bl_u + boff);
            }
#pragma unroll
            for (int mt = 0; mt < 2; mt++) {
#pragma unroll
                for (int n8 = 0; n8 < 4; n8++) {
                    int ng = n8 >> 1, sb = (n8 & 1) * 2;
                    mma_bf16(acc[mt][n8], afh[mt], bfh[ng][sb], bfh[ng][sb + 1]);
                    mma_bf16(acc[mt][n8], afh[mt], bfl[ng][sb], bfl[ng][sb + 1]);
                    mma_bf16(acc[mt][n8], afl[mt], bfh[ng][sb], bfh[ng][sb + 1]);
                }
            }
        }

        // ---- Epilogue on last chunk of the tile ----
        if (c == NCHUNK - 1) {
#pragma unroll
            for (int mt = 0; mt < 2; mt++) {
                int r0w = row0 + wm * 32 + mt * 16 + (lane >> 2);
#pragma unroll
                for (int n8 = 0; n8 < 4; n8++) {
                    int col = wn * 32 + n8 * 8 + (lane & 3) * 2;
                    float2 o0, o1;
                    o0.x = fmaxf(acc[mt][n8][0] + bv[n8].x, 0.f);
                    o0.y = fmaxf(acc[mt][n8][1] + bv[n8].y, 0.f);
                    o1.x = fmaxf(acc[mt][n8][2] + bv[n8].x, 0.f);
                    o1.y = fmaxf(acc[mt][n8][3] + bv[n8].y, 0.f);
                    if (r0w < N)
                        *reinterpret_cast<float2*>(dst + (size_t)r0w * 128 + col) = o0;
                    if (r0w + 8 < N)
                        *reinterpret_cast<float2*>(dst + (size_t)(r0w + 8) * 128 + col) = o1;
                    acc[mt][n8][0] = 0.f; acc[mt][n8][1] = 0.f;
                    acc[mt][n8][2] = 0.f; acc[mt][n8][3] = 0.f;
                }
            }
        }
    }
}

// Fused projections (512 threads): bid 0-50 user (K=128), 51-151 content (K=256)
__global__ void __launch_bounds__(512, 1)
proj_fused(const float* __restrict__ xc, const float* __restrict__ xu,
           const float* __restrict__ Wc, const float* __restrict__ bc,
           const float* __restrict__ Wu, const float* __restrict__ bu,
           int Nc, int Nu) {
    extern __shared__ char smc[];
    if (blockIdx.x < 51)
        run_proj<128>(xu, Wu, bu, g_hu, Nu, blockIdx.x, 51, smc);
    else
        run_proj<256>(xc, Wc, bc, g_hc, Nc, blockIdx.x - 51, 101, smc);
}

// ============================================================================
// Combine + output fused (round-7 version, unchanged from 334us best).
// ============================================================================
__global__ void __launch_bounds__(256, 1)
combine_kernel(const float* __restrict__ Wl, const float* __restrict__ bl,
               const float* __restrict__ Wr, const float* __restrict__ Wo,
               const float* __restrict__ bo, float* __restrict__ out, int N) {
    constexpr int PITCH = 136, OPITCH = 72;
    extern __shared__ char smc[];
    __nv_bfloat16* Bh = reinterpret_cast<__nv_bfloat16*>(smc);
    __nv_bfloat16* Bl_ = Bh + 256 * PITCH;
    __nv_bfloat16* Ah = Bl_ + 256 * PITCH;
    __nv_bfloat16* Al = Ah + 64 * PITCH;
    __nv_bfloat16* Oh = Al + 64 * PITCH;
    __nv_bfloat16* Ol = Oh + 128 * OPITCH;

    const int t = threadIdx.x;
    const int wid = t >> 5, lane = t & 31;
    const int wm = wid >> 1, wn = wid & 1;

    for (int i = t; i < 256 * 32; i += 256) {
        int k = i >> 5, n4 = (i & 31) * 4;
        const float* wsrc = (k < 128) ? Wl + (size_t)k * 128
                                      : Wr + (size_t)(k - 128) * 128;
        float4 w = *reinterpret_cast<const float4*>(wsrc + n4);
        uint2 hv, lv;
        cvt_hl4(w, hv, lv);
        *reinterpret_cast<uint2*>(Bh + k * PITCH + n4) = hv;
        *reinterpret_cast<uint2*>(Bl_ + k * PITCH + n4) = lv;
    }
    for (int i = t; i < 128 * 16; i += 256) {
        int k = i >> 4, n4 = (i & 15) * 4;
        float4 w = *reinterpret_cast<const float4*>(Wo + (size_t)k * 64 + n4);
        uint2 hv, lv;
        cvt_hl4(w, hv, lv);
        *reinterpret_cast<uint2*>(Oh + k * OPITCH + n4) = hv;
        *reinterpret_cast<uint2*>(Ol + k * OPITCH + n4) = lv;
    }

    const uint32_t ah_u = smem_u32(Ah), al_u = smem_u32(Al);
    const uint32_t bh_u = smem_u32(Bh), bl_u = smem_u32(Bl_);
    const uint32_t oh_u = smem_u32(Oh), ol_u = smem_u32(Ol);
    const int a_row_l = lane & 15, a_col_l = (lane >> 4) * 8;
    const int b_k_l = (lane & 7) + ((lane >> 3) & 1) * 8;
    const int b_n_l = (lane >> 4) * 8;

    float2 blv[8];
#pragma unroll
    for (int n8 = 0; n8 < 8; n8++)
        blv[n8] = *reinterpret_cast<const float2*>(bl + wn * 64 + n8 * 8 +
                                                   (lane & 3) * 2);
    float2 bov[4];
#pragma unroll
    for (int n8 = 0; n8 < 4; n8++)
        bov[n8] = *reinterpret_cast<const float2*>(bo + wn * 32 + n8 * 8 +
                                                   (lane & 3) * 2);

    const int ntiles = (N + 63) >> 6;
    for (int tile = blockIdx.x; tile < ntiles; tile += gridDim.x) {
        const int row0 = tile << 6;
        float acc[8][4];
#pragma unroll
        for (int n8 = 0; n8 < 8; n8++)
#pragma unroll
            for (int e = 0; e < 4; e++) acc[n8][e] = 0.f;

        for (int c = 0; c < 2; ++c) {
            __syncthreads();
            const float* src = (c == 0) ? g_mean : g_hc;
            float4 vv[8];
#pragma unroll
            for (int it = 0; it < 8; it++) {
                int i = t + it * 256;
                int rr = row0 + (i >> 5), c4 = (i & 31) * 4;
                vv[it] = (rr < N) ? *reinterpret_cast<const float4*>(
                                        src + (size_t)rr * 128 + c4)
                                  : make_float4(0.f, 0.f, 0.f, 0.f);
            }
#pragma unroll
            for (int it = 0; it < 8; it++) {
                int i = t + it * 256;
                int r = i >> 5, c4 = (i & 31) * 4;
                uint2 hv, lv;
                cvt_hl4(vv[it], hv, lv);
                *reinterpret_cast<uint2*>(Ah + r * PITCH + c4) = hv;
                *reinterpret_cast<uint2*>(Al + r * PITCH + c4) = lv;
            }
            __syncthreads();
#pragma unroll 1
            for (int k0 = 0; k0 < 128; k0 += 16) {
                uint32_t afh[4], afl[4];
                uint32_t aoff = (uint32_t)((wm * 16 + a_row_l) * PITCH + k0 + a_col_l) * 2;
                ldsm_x4(afh, ah_u + aoff);
                ldsm_x4(afl, al_u + aoff);
                uint32_t bfh[4][4], bfl[4][4];
#pragma unroll
                for (int ng = 0; ng < 4; ng++) {
                    uint32_t boff = (uint32_t)((c * 128 + k0 + b_k_l) * PITCH +
                                               wn * 64 + ng * 16 + b_n_l) * 2;
                    ldsm_x4_t(bfh[ng], bh_u + boff);
                    ldsm_x4_t(bfl[ng], bl_u + boff);
                }
#pragma unroll
                for (int n8 = 0; n8 < 8; n8++) {
                    int ng = n8 >> 1, sb = (n8 & 1) * 2;
                    mma_bf16(acc[n8], afh, bfh[ng][sb], bfh[ng][sb + 1]);
                    mma_bf16(acc[n8], afh, bfl[ng][sb], bfl[ng][sb + 1]);
                    mma_bf16(acc[n8], afl, bfh[ng][sb], bfh[ng][sb + 1]);
                }
            }
        }
        __syncthreads();

        {
            int r1 = wm * 16 + (lane >> 2);
#pragma unroll
            for (int n8 = 0; n8 < 8; n8++) {
                int col = wn * 64 + n8 * 8 + (lane & 3) * 2;
                uint32_t hv, lv;
                cvt_hl2(acc[n8][0] + blv[n8].x, acc[n8][1] + blv[n8].y, hv, lv);
                *reinterpret_cast<uint32_t*>(Ah + r1 * PITCH + col) = hv;
                *reinterpret_cast<uint32_t*>(Al + r1 * PITCH + col) = lv;
                cvt_hl2(acc[n8][2] + blv[n8].x, acc[n8][3] + blv[n8].y, hv, lv);
                *reinterpret_cast<uint32_t*>(Ah + (r1 + 8) * PITCH + col) = hv;
                *reinterpret_cast<uint32_t*>(Al + (r1 + 8) * PITCH + col) = lv;
            }
        }
        __syncthreads();

        float acc2[4][4];
#pragma unroll
        for (int n8 = 0; n8 < 4; n8++)
#pragma unroll
            for (int e = 0; e < 4; e++) acc2[n8][e] = 0.f;
#pragma unroll 1
        for (int k0 = 0; k0 < 128; k0 += 16) {
            uint32_t afh[4], afl[4];
            uint32_t aoff = (uint32_t)((wm * 16 + a_row_l) * PITCH + k0 + a_col_l) * 2;
            ldsm_x4(afh, ah_u + aoff);
            ldsm_x4(afl, al_u + aoff);
            uint32_t bfh[2][4], bfl[2][4];
#pragma unroll
            for (int ng = 0; ng < 2; ng++) {
                uint32_t boff = (uint32_t)((k0 + b_k_l) * OPITCH +
                                           wn * 32 + ng * 16 + b_n_l) * 2;
                ldsm_x4_t(bfh[ng], oh_u + boff);
                ldsm_x4_t(bfl[ng], ol_u + boff);
            }
#pragma unroll
            for (int n8 = 0; n8 < 4; n8++) {
                int ng = n8 >> 1, sb = (n8 & 1) * 2;
                mma_bf16(acc2[n8], afh, bfh[ng][sb], bfh[ng][sb + 1]);
                mma_bf16(acc2[n8], afh, bfl[ng][sb], bfl[ng][sb + 1]);
                mma_bf16(acc2[n8], afl, bfh[ng][sb], bfh[ng][sb + 1]);
            }
        }
        int r0w = row0 + wm * 16 + (lane >> 2);
#pragma unroll
        for (int n8 = 0; n8 < 4; n8++) {
            int col = wn * 32 + n8 * 8 + (lane & 3) * 2;
            float2 o0, o1;
            o0.x = acc2[n8][0] + bov[n8].x;
            o0.y = acc2[n8][1] + bov[n8].y;
            o1.x = acc2[n8][2] + bov[n8].x;
            o1.y = acc2[n8][3] + bov[n8].y;
            if (r0w < N)
                *reinterpret_cast<float2*>(out + (size_t)r0w * 64 + col) = o0;
            if (r0w + 8 < N)
                *reinterpret_cast<float2*>(out + (size_t)(r0w + 8) * 64 + col) = o1;
        }
    }
}

// ============================ CSR build =====================================
__global__ void zero_deg_kernel(int nc) {
    int i = blockIdx.x * blockDim.x + threadIdx.x;
    int stride = gridDim.x * blockDim.x;
    for (; i < nc; i += stride) g_deg[i] = 0;
}
__global__ void hist_kernel(const int* __restrict__ ei, int E) {
    int i = blockIdx.x * blockDim.x + threadIdx.x;
    if (i < E) atomicAdd(&g_deg[ei[E + i]], 1);
}
__global__ void scan1_kernel(int nc) {
    __shared__ int s[256];
    int t = threadIdx.x;
    int i = blockIdx.x * 256 + t;
    s[t] = (i < nc) ? g_deg[i] : 0;
    __syncthreads();
    for (int d = 128; d > 0; d >>= 1) {
        if (t < d) s[t] += s[t + d];
        __syncthreads();
    }
    if (t == 0) g_bsum[blockIdx.x] = s[0];
}
__global__ void scan2_kernel(int nb) {
    __shared__ int s[512];
    int t = threadIdx.x;
    int v = (t < nb) ? g_bsum[t] : 0;
    s[t] = v;
    __syncthreads();
    for (int d = 1; d < 512; d <<= 1) {
        int add = (t >= d) ? s[t - d] : 0;
        __syncthreads();
        s[t] += add;
        __syncthreads();
    }
    if (t < nb) g_bsum[t] = s[t] - v;
}
__global__ void scan3_kernel(int nc) {
    __shared__ int s[256];
    int t = threadIdx.x;
    int i = blockIdx.x * 256 + t;
    int v = (i < nc) ? g_deg[i] : 0;
    s[t] = v;
    __syncthreads();
    for (int d = 1; d < 256; d <<= 1) {
        int add = (t >= d) ? s[t - d] : 0;
        __syncthreads();
        s[t] += add;
        __syncthreads();
    }
    if (i < nc) {
        int off = g_bsum[blockIdx.x] + s[t] - v;
        g_off[i] = off;
        g_cursor[i] = off;
    }
}
__global__ void fill_kernel(const int* __restrict__ ei, int E) {
    int i = blockIdx.x * blockDim.x + threadIdx.x;
    if (i < E) {
        int dst = ei[E + i];
        int pos = atomicAdd(&g_cursor[dst], 1);
        g_csr[pos] = ei[i];
    }
}

// ------------------- Gather-mean: warp per content node --------------------
__global__ void agg_kernel(int nc) {
    const int warp = (blockIdx.x * blockDim.x + threadIdx.x) >> 5;
    const int lane = threadIdx.x & 31;
    if (warp >= nc) return;
    const int s0 = g_off[warp];
    const int d = g_deg[warp];
    float4 acc = make_float4(0.f, 0.f, 0.f, 0.f);
    for (int base = 0; base < d; base += 32) {
        int my = (base + lane < d) ? g_csr[s0 + base + lane] : 0;
        int lim = min(32, d - base);
        for (int j = 0; j < lim; j++) {
            int nbr = __shfl_sync(0xffffffffu, my, j);
            float4 v = reinterpret_cast<const float4*>(g_hu + (size_t)nbr * H)[lane];
            acc.x += v.x; acc.y += v.y; acc.z += v.z; acc.w += v.w;
        }
    }
    float inv = 1.f / fmaxf((float)d, 1.f);
    acc.x *= inv; acc.y *= inv; acc.z *= inv; acc.w *= inv;
    reinterpret_cast<float4*>(g_mean + (size_t)warp * H)[lane] = acc;
}

// ---------------------------------------------------------------------------
extern "C" void kernel_launch(void* const* d_in, const int* in_sizes, int n_in,
                              void* d_out, int out_size) {
    const float* x_content = (const float*)d_in[0];
    const float* x_user    = (const float*)d_in[1];
    const int*   ei        = (const int*)d_in[2];   // int32 (JAX x64 off)
    const float* Wc = (const float*)d_in[3];
    const float* bc = (const float*)d_in[4];
    const float* Wu = (const float*)d_in[5];
    const float* bu = (const float*)d_in[6];
    const float* Wl = (const float*)d_in[7];
    const float* bl = (const float*)d_in[8];
    const float* Wr = (const float*)d_in[9];
    const float* Wo = (const float*)d_in[10];
    const float* bo = (const float*)d_in[11];
    float* out = (float*)d_out;

    const int Nc = in_sizes[0] / 256;
    const int Nu = in_sizes[1] / 128;
    const int E  = in_sizes[2] / 2;

    // proj (content): B 2*256*136*2 + A 2*128*136*2 = 208896 (1 CTA/SM, 512 thr)
    const int smem_proj = (2 * 256 * 136 + 2 * 128 * 136) * 2;
    // combine (round 7): 210944
    const int smem_comb = (2 * 256 * 136 + 2 * 64 * 136 + 2 * 128 * 72) * 2;

    cudaFuncSetAttribute(proj_fused,
                         cudaFuncAttributeMaxDynamicSharedMemorySize, smem_proj);
    cudaFuncSetAttribute(combine_kernel,
                         cudaFuncAttributeMaxDynamicSharedMemorySize, smem_comb);

    const int nb = (Nc + 255) / 256;  // <= 512

    zero_deg_kernel<<<256, 256>>>(Nc);
    hist_kernel<<<(E + 255) / 256, 256>>>(ei, E);
    scan1_kernel<<<nb, 256>>>(Nc);
    proj_fused<<<152, 512, smem_proj>>>(x_content, x_user, Wc, bc, Wu, bu, Nc, Nu);
    scan2_kernel<<<1, 512>>>(nb);
    scan3_kernel<<<nb, 256>>>(Nc);
    fill_kernel<<<(E + 255) / 256, 256>>>(ei, E);
    agg_kernel<<<(Nc * 32 + 255) / 256, 256>>>(Nc);
    combine_kernel<<<152, 256, smem_comb>>>(Wl, bl, Wr, Wo, bo, out, Nc);
}

// round 14
// speedup vs baseline: 1.0552x; 1.0320x over previous
#include <cuda_runtime.h>
#include <cuda_bf16.h>
#include <stdint.h>

#define H      128
#define NC_MAX 100000
#define NU_MAX 100000
#define E_MAX  1600000

// Scratch: __device__ globals (allocation-free rule)
__device__ __align__(16) float g_hu[(size_t)NU_MAX * H];
__device__ __align__(16) float g_hc[(size_t)NC_MAX * H];
__device__ __align__(16) float g_mean[(size_t)NC_MAX * H];
__device__ int g_deg[NC_MAX];
__device__ int g_off[NC_MAX];
__device__ int g_cursor[NC_MAX];
__device__ int g_csr[E_MAX];
__device__ int g_bsum[512];

// ============================= PTX helpers (portable) =======================
__device__ __forceinline__ uint32_t smem_u32(const void* p) {
    uint32_t a;
    asm("{ .reg .u64 t; cvta.to.shared.u64 t, %1; cvt.u32.u64 %0, t; }"
        : "=r"(a) : "l"(p));
    return a;
}
__device__ __forceinline__ void ldsm_x4(uint32_t* r, uint32_t addr) {
    asm volatile("ldmatrix.sync.aligned.m8n8.x4.shared.b16 {%0,%1,%2,%3}, [%4];"
                 : "=r"(r[0]), "=r"(r[1]), "=r"(r[2]), "=r"(r[3]) : "r"(addr));
}
__device__ __forceinline__ void ldsm_x4_t(uint32_t* r, uint32_t addr) {
    asm volatile("ldmatrix.sync.aligned.m8n8.x4.trans.shared.b16 {%0,%1,%2,%3}, [%4];"
                 : "=r"(r[0]), "=r"(r[1]), "=r"(r[2]), "=r"(r[3]) : "r"(addr));
}
__device__ __forceinline__ void mma_bf16(float* d, const uint32_t* a,
                                         uint32_t b0, uint32_t b1) {
    asm volatile(
        "mma.sync.aligned.m16n8k16.row.col.f32.bf16.bf16.f32 "
        "{%0,%1,%2,%3}, {%4,%5,%6,%7}, {%8,%9}, {%0,%1,%2,%3};"
        : "+f"(d[0]), "+f"(d[1]), "+f"(d[2]), "+f"(d[3])
        : "r"(a[0]), "r"(a[1]), "r"(a[2]), "r"(a[3]), "r"(b0), "r"(b1));
}

// fp32 -> (bf16 hi, bf16 lo), packed
__device__ __forceinline__ void cvt_hl4(float4 v, uint2& hv, uint2& lv) {
    float f[4] = {v.x, v.y, v.z, v.w};
    uint32_t h[4], l[4];
#pragma unroll
    for (int j = 0; j < 4; j++) {
        __nv_bfloat16 hb = __float2bfloat16_rn(f[j]);
        float hf = __bfloat162float(hb);
        __nv_bfloat16 lb = __float2bfloat16_rn(f[j] - hf);
        h[j] = (uint32_t)__bfloat16_as_ushort(hb);
        l[j] = (uint32_t)__bfloat16_as_ushort(lb);
    }
    hv = make_uint2(h[0] | (h[1] << 16), h[2] | (h[3] << 16));
    lv = make_uint2(l[0] | (l[1] << 16), l[2] | (l[3] << 16));
}
__device__ __forceinline__ void cvt_hl2(float a, float b, uint32_t& hv, uint32_t& lv) {
    __nv_bfloat16 h0 = __float2bfloat16_rn(a), h1 = __float2bfloat16_rn(b);
    float f0 = __bfloat162float(h0), f1 = __bfloat162float(h1);
    __nv_bfloat16 l0 = __float2bfloat16_rn(a - f0), l1 = __float2bfloat16_rn(b - f1);
    hv = (uint32_t)__bfloat16_as_ushort(h0) |
         ((uint32_t)__bfloat16_as_ushort(h1) << 16);
    lv = (uint32_t)__bfloat16_as_ushort(l0) |
         ((uint32_t)__bfloat16_as_ushort(l1) << 16);
}

// ============================================================================
// Projection (PIPELINED, round-11 exact): relu(X @ W + b) -> dst. 64-row
// tiles, 16x64 warp tiles, double-buffered A (hi/lo). Per chunk g: MMA(g)
// overlaps convert(g+1) (other parity) and LDG(g+2) (regs). One sync/chunk.
// ============================================================================
template <int KTOT>
__device__ void run_proj(const float* __restrict__ X, const float* __restrict__ W,
                         const float* __restrict__ bias, float* __restrict__ dst,
                         int N, int bid, int nb, char* smc) {
    constexpr int NCHUNK = KTOT / 128;
    constexpr int PITCH = 136;
    constexpr int ABUF = 2 * 64 * PITCH;  // bf16 elems per buffer (hi+lo)
    __nv_bfloat16* Bh = reinterpret_cast<__nv_bfloat16*>(smc);
    __nv_bfloat16* Bl = Bh + KTOT * PITCH;
    __nv_bfloat16* Abase = Bl + KTOT * PITCH;  // 2 buffers of ABUF

    const int t = threadIdx.x;
    const int wid = t >> 5, lane = t & 31;
    const int wm = wid >> 1, wn = wid & 1;

    // Stage weights hi/lo
    for (int i = t; i < KTOT * 32; i += 256) {
        int k = i >> 5, n4 = (i & 31) * 4;
        float4 w = *reinterpret_cast<const float4*>(W + (size_t)k * 128 + n4);
        uint2 hv, lv;
        cvt_hl4(w, hv, lv);
        *reinterpret_cast<uint2*>(Bh + k * PITCH + n4) = hv;
        *reinterpret_cast<uint2*>(Bl + k * PITCH + n4) = lv;
    }

    const uint32_t ab_u = smem_u32(Abase);
    const uint32_t bh_u = smem_u32(Bh), bl_u = smem_u32(Bl);
    const int a_row_l = lane & 15, a_col_l = (lane >> 4) * 8;
    const int b_k_l = (lane & 7) + ((lane >> 3) & 1) * 8;
    const int b_n_l = (lane >> 4) * 8;

    float2 bv[8];
#pragma unroll
    for (int n8 = 0; n8 < 8; n8++)
        bv[n8] = *reinterpret_cast<const float2*>(bias + wn * 64 + n8 * 8 +
                                                  (lane & 3) * 2);

    const int ntiles = (N + 63) >> 6;
    const int nloc = (ntiles > bid) ? (ntiles - 1 - bid) / nb + 1 : 0;
    const int total = nloc * NCHUNK;

    float4 vv[8];
    auto ldg_chunk = [&](int g) {
        const int tile = bid + (g / NCHUNK) * nb;
        const int c = g % NCHUNK;
        const int row0 = tile << 6;
#pragma unroll
        for (int it = 0; it < 8; it++) {
            int i = t + it * 256;
            int rr = row0 + (i >> 5), c4 = (i & 31) * 4;
            vv[it] = (rr < N) ? *reinterpret_cast<const float4*>(
                                    X + (size_t)rr * KTOT + c * 128 + c4)
                              : make_float4(0.f, 0.f, 0.f, 0.f);
        }
    };
    auto cvt_chunk = [&](int g) {
        __nv_bfloat16* Ah = Abase + (g & 1) * ABUF;
        __nv_bfloat16* Al = Ah + 64 * PITCH;
#pragma unroll
        for (int it = 0; it < 8; it++) {
            int i = t + it * 256;
            int r = i >> 5, c4 = (i & 31) * 4;
            uint2 hv, lv;
            cvt_hl4(vv[it], hv, lv);
            *reinterpret_cast<uint2*>(Ah + r * PITCH + c4) = hv;
            *reinterpret_cast<uint2*>(Al + r * PITCH + c4) = lv;
        }
    };

    if (total > 0) {
        ldg_chunk(0);
        cvt_chunk(0);
        if (total > 1) ldg_chunk(1);
    }
    __syncthreads();

    float acc[8][4];
#pragma unroll
    for (int n8 = 0; n8 < 8; n8++)
#pragma unroll
        for (int e = 0; e < 4; e++) acc[n8][e] = 0.f;

    for (int g = 0; g < total; g++) {
        const int tile = bid + (g / NCHUNK) * nb;
        const int c = g % NCHUNK;
        const uint32_t ah_u = ab_u + (uint32_t)(g & 1) * ABUF * 2;
        const uint32_t al_u = ah_u + 64 * PITCH * 2;

#pragma unroll 1
        for (int k0 = 0; k0 < 128; k0 += 16) {
            uint32_t afh[4], afl[4];
            uint32_t aoff = (uint32_t)((wm * 16 + a_row_l) * PITCH + k0 + a_col_l) * 2;
            ldsm_x4(afh, ah_u + aoff);
            ldsm_x4(afl, al_u + aoff);
            uint32_t bfh[4][4], bfl[4][4];
#pragma unroll
            for (int ng = 0; ng < 4; ng++) {
                uint32_t boff = (uint32_t)((c * 128 + k0 + b_k_l) * PITCH +
                                           wn * 64 + ng * 16 + b_n_l) * 2;
                ldsm_x4_t(bfh[ng], bh_u + boff);
                ldsm_x4_t(bfl[ng], bl_u + boff);
            }
#pragma unroll
            for (int n8 = 0; n8 < 8; n8++) {
                int ng = n8 >> 1, sb = (n8 & 1) * 2;
                mma_bf16(acc[n8], afh, bfh[ng][sb], bfh[ng][sb + 1]);
                mma_bf16(acc[n8], afh, bfl[ng][sb], bfl[ng][sb + 1]);
                mma_bf16(acc[n8], afl, bfh[ng][sb], bfh[ng][sb + 1]);
            }
        }

        if (g + 1 < total) cvt_chunk(g + 1);
        if (g + 2 < total) ldg_chunk(g + 2);

        if (c == NCHUNK - 1) {
            const int row0 = tile << 6;
            int r0w = row0 + wm * 16 + (lane >> 2);
#pragma unroll
            for (int n8 = 0; n8 < 8; n8++) {
                int col = wn * 64 + n8 * 8 + (lane & 3) * 2;
                float2 o0, o1;
                o0.x = fmaxf(acc[n8][0] + bv[n8].x, 0.f);
                o0.y = fmaxf(acc[n8][1] + bv[n8].y, 0.f);
                o1.x = fmaxf(acc[n8][2] + bv[n8].x, 0.f);
                o1.y = fmaxf(acc[n8][3] + bv[n8].y, 0.f);
                if (r0w < N)
                    *reinterpret_cast<float2*>(dst + (size_t)r0w * 128 + col) = o0;
                if (r0w + 8 < N)
                    *reinterpret_cast<float2*>(dst + (size_t)(r0w + 8) * 128 + col) = o1;
            }
#pragma unroll
            for (int n8 = 0; n8 < 8; n8++)
#pragma unroll
                for (int e = 0; e < 4; e++) acc[n8][e] = 0.f;
        }
        __syncthreads();
    }
}

// Fused projections: blocks 0-50 -> user (K=128), 51-151 -> content (K=256)
__global__ void __launch_bounds__(256, 1)
proj_fused(const float* __restrict__ xc, const float* __restrict__ xu,
           const float* __restrict__ Wc, const float* __restrict__ bc,
           const float* __restrict__ Wu, const float* __restrict__ bu,
           int Nc, int Nu) {
    extern __shared__ char smc[];
    if (blockIdx.x < 51)
        run_proj<128>(xu, Wu, bu, g_hu, Nu, blockIdx.x, 51, smc);
    else
        run_proj<256>(xc, Wc, bc, g_hc, Nc, blockIdx.x - 51, 101, smc);
}

// ============================================================================
// Combine + output fused (round-7 version, unchanged from 334us best).
// ============================================================================
__global__ void __launch_bounds__(256, 1)
combine_kernel(const float* __restrict__ Wl, const float* __restrict__ bl,
               const float* __restrict__ Wr, const float* __restrict__ Wo,
               const float* __restrict__ bo, float* __restrict__ out, int N) {
    constexpr int PITCH = 136, OPITCH = 72;
    extern __shared__ char smc[];
    __nv_bfloat16* Bh = reinterpret_cast<__nv_bfloat16*>(smc);
    __nv_bfloat16* Bl_ = Bh + 256 * PITCH;
    __nv_bfloat16* Ah = Bl_ + 256 * PITCH;
    __nv_bfloat16* Al = Ah + 64 * PITCH;
    __nv_bfloat16* Oh = Al + 64 * PITCH;
    __nv_bfloat16* Ol = Oh + 128 * OPITCH;

    const int t = threadIdx.x;
    const int wid = t >> 5, lane = t & 31;
    const int wm = wid >> 1, wn = wid & 1;

    for (int i = t; i < 256 * 32; i += 256) {
        int k = i >> 5, n4 = (i & 31) * 4;
        const float* wsrc = (k < 128) ? Wl + (size_t)k * 128
                                      : Wr + (size_t)(k - 128) * 128;
        float4 w = *reinterpret_cast<const float4*>(wsrc + n4);
        uint2 hv, lv;
        cvt_hl4(w, hv, lv);
        *reinterpret_cast<uint2*>(Bh + k * PITCH + n4) = hv;
        *reinterpret_cast<uint2*>(Bl_ + k * PITCH + n4) = lv;
    }
    for (int i = t; i < 128 * 16; i += 256) {
        int k = i >> 4, n4 = (i & 15) * 4;
        float4 w = *reinterpret_cast<const float4*>(Wo + (size_t)k * 64 + n4);
        uint2 hv, lv;
        cvt_hl4(w, hv, lv);
        *reinterpret_cast<uint2*>(Oh + k * OPITCH + n4) = hv;
        *reinterpret_cast<uint2*>(Ol + k * OPITCH + n4) = lv;
    }

    const uint32_t ah_u = smem_u32(Ah), al_u = smem_u32(Al);
    const uint32_t bh_u = smem_u32(Bh), bl_u = smem_u32(Bl_);
    const uint32_t oh_u = smem_u32(Oh), ol_u = smem_u32(Ol);
    const int a_row_l = lane & 15, a_col_l = (lane >> 4) * 8;
    const int b_k_l = (lane & 7) + ((lane >> 3) & 1) * 8;
    const int b_n_l = (lane >> 4) * 8;

    float2 blv[8];
#pragma unroll
    for (int n8 = 0; n8 < 8; n8++)
        blv[n8] = *reinterpret_cast<const float2*>(bl + wn * 64 + n8 * 8 +
                                                   (lane & 3) * 2);
    float2 bov[4];
#pragma unroll
    for (int n8 = 0; n8 < 4; n8++)
        bov[n8] = *reinterpret_cast<const float2*>(bo + wn * 32 + n8 * 8 +
                                                   (lane & 3) * 2);

    const int ntiles = (N + 63) >> 6;
    for (int tile = blockIdx.x; tile < ntiles; tile += gridDim.x) {
        const int row0 = tile << 6;
        float acc[8][4];
#pragma unroll
        for (int n8 = 0; n8 < 8; n8++)
#pragma unroll
            for (int e = 0; e < 4; e++) acc[n8][e] = 0.f;

        for (int c = 0; c < 2; ++c) {
            __syncthreads();
            const float* src = (c == 0) ? g_mean : g_hc;
            float4 vv[8];
#pragma unroll
            for (int it = 0; it < 8; it++) {
                int i = t + it * 256;
                int rr = row0 + (i >> 5), c4 = (i & 31) * 4;
                vv[it] = (rr < N) ? *reinterpret_cast<const float4*>(
                                        src + (size_t)rr * 128 + c4)
                                  : make_float4(0.f, 0.f, 0.f, 0.f);
            }
#pragma unroll
            for (int it = 0; it < 8; it++) {
                int i = t + it * 256;
                int r = i >> 5, c4 = (i & 31) * 4;
                uint2 hv, lv;
                cvt_hl4(vv[it], hv, lv);
                *reinterpret_cast<uint2*>(Ah + r * PITCH + c4) = hv;
                *reinterpret_cast<uint2*>(Al + r * PITCH + c4) = lv;
            }
            __syncthreads();
#pragma unroll 1
            for (int k0 = 0; k0 < 128; k0 += 16) {
                uint32_t afh[4], afl[4];
                uint32_t aoff = (uint32_t)((wm * 16 + a_row_l) * PITCH + k0 + a_col_l) * 2;
                ldsm_x4(afh, ah_u + aoff);
                ldsm_x4(afl, al_u + aoff);
                uint32_t bfh[4][4], bfl[4][4];
#pragma unroll
                for (int ng = 0; ng < 4; ng++) {
                    uint32_t boff = (uint32_t)((c * 128 + k0 + b_k_l) * PITCH +
                                               wn * 64 + ng * 16 + b_n_l) * 2;
                    ldsm_x4_t(bfh[ng], bh_u + boff);
                    ldsm_x4_t(bfl[ng], bl_u + boff);
                }
#pragma unroll
                for (int n8 = 0; n8 < 8; n8++) {
                    int ng = n8 >> 1, sb = (n8 & 1) * 2;
                    mma_bf16(acc[n8], afh, bfh[ng][sb], bfh[ng][sb + 1]);
                    mma_bf16(acc[n8], afh, bfl[ng][sb], bfl[ng][sb + 1]);
                    mma_bf16(acc[n8], afl, bfh[ng][sb], bfh[ng][sb + 1]);
                }
            }
        }
        __syncthreads();

        {
            int r1 = wm * 16 + (lane >> 2);
#pragma unroll
            for (int n8 = 0; n8 < 8; n8++) {
                int col = wn * 64 + n8 * 8 + (lane & 3) * 2;
                uint32_t hv, lv;
                cvt_hl2(acc[n8][0] + blv[n8].x, acc[n8][1] + blv[n8].y, hv, lv);
                *reinterpret_cast<uint32_t*>(Ah + r1 * PITCH + col) = hv;
                *reinterpret_cast<uint32_t*>(Al + r1 * PITCH + col) = lv;
                cvt_hl2(acc[n8][2] + blv[n8].x, acc[n8][3] + blv[n8].y, hv, lv);
                *reinterpret_cast<uint32_t*>(Ah + (r1 + 8) * PITCH + col) = hv;
                *reinterpret_cast<uint32_t*>(Al + (r1 + 8) * PITCH + col) = lv;
            }
        }
        __syncthreads();

        float acc2[4][4];
#pragma unroll
        for (int n8 = 0; n8 < 4; n8++)
#pragma unroll
            for (int e = 0; e < 4; e++) acc2[n8][e] = 0.f;
#pragma unroll 1
        for (int k0 = 0; k0 < 128; k0 += 16) {
            uint32_t afh[4], afl[4];
            uint32_t aoff = (uint32_t)((wm * 16 + a_row_l) * PITCH + k0 + a_col_l) * 2;
            ldsm_x4(afh, ah_u + aoff);
            ldsm_x4(afl, al_u + aoff);
            uint32_t bfh[2][4], bfl[2][4];
#pragma unroll
            for (int ng = 0; ng < 2; ng++) {
                uint32_t boff = (uint32_t)((k0 + b_k_l) * OPITCH +
                                           wn * 32 + ng * 16 + b_n_l) * 2;
                ldsm_x4_t(bfh[ng], oh_u + boff);
                ldsm_x4_t(bfl[ng], ol_u + boff);
            }
#pragma unroll
            for (int n8 = 0; n8 < 4; n8++) {
                int ng = n8 >> 1, sb = (n8 & 1) * 2;
                mma_bf16(acc2[n8], afh, bfh[ng][sb], bfh[ng][sb + 1]);
                mma_bf16(acc2[n8], afh, bfl[ng][sb], bfl[ng][sb + 1]);
                mma_bf16(acc2[n8], afl, bfh[ng][sb], bfh[ng][sb + 1]);
            }
        }
        int r0w = row0 + wm * 16 + (lane >> 2);
#pragma unroll
        for (int n8 = 0; n8 < 4; n8++) {
            int col = wn * 32 + n8 * 8 + (lane & 3) * 2;
            float2 o0, o1;
            o0.x = acc2[n8][0] + bov[n8].x;
            o0.y = acc2[n8][1] + bov[n8].y;
            o1.x = acc2[n8][2] + bov[n8].x;
            o1.y = acc2[n8][3] + bov[n8].y;
            if (r0w < N)
                *reinterpret_cast<float2*>(out + (size_t)r0w * 64 + col) = o0;
            if (r0w + 8 < N)
                *reinterpret_cast<float2*>(out + (size_t)(r0w + 8) * 64 + col) = o1;
        }
    }
}

// ============================ CSR build =====================================
__global__ void zero_deg_kernel(int nc) {
    int i = blockIdx.x * blockDim.x + threadIdx.x;
    int stride = gridDim.x * blockDim.x;
    for (; i < nc; i += stride) g_deg[i] = 0;
}
__global__ void hist_kernel(const int* __restrict__ ei, int E) {
    int i = blockIdx.x * blockDim.x + threadIdx.x;
    if (i < E) atomicAdd(&g_deg[ei[E + i]], 1);
}
__global__ void scan1_kernel(int nc) {
    __shared__ int s[256];
    int t = threadIdx.x;
    int i = blockIdx.x * 256 + t;
    s[t] = (i < nc) ? g_deg[i] : 0;
    __syncthreads();
    for (int d = 128; d > 0; d >>= 1) {
        if (t < d) s[t] += s[t + d];
        __syncthreads();
    }
    if (t == 0) g_bsum[blockIdx.x] = s[0];
}
__global__ void scan2_kernel(int nb) {
    __shared__ int s[512];
    int t = threadIdx.x;
    int v = (t < nb) ? g_bsum[t] : 0;
    s[t] = v;
    __syncthreads();
    for (int d = 1; d < 512; d <<= 1) {
        int add = (t >= d) ? s[t - d] : 0;
        __syncthreads();
        s[t] += add;
        __syncthreads();
    }
    if (t < nb) g_bsum[t] = s[t] - v;
}
__global__ void scan3_kernel(int nc) {
    __shared__ int s[256];
    int t = threadIdx.x;
    int i = blockIdx.x * 256 + t;
    int v = (i < nc) ? g_deg[i] : 0;
    s[t] = v;
    __syncthreads();
    for (int d = 1; d < 256; d <<= 1) {
        int add = (t >= d) ? s[t - d] : 0;
        __syncthreads();
        s[t] += add;
        __syncthreads();
    }
    if (i < nc) {
        int off = g_bsum[blockIdx.x] + s[t] - v;
        g_off[i] = off;
        g_cursor[i] = off;
    }
}
__global__ void fill_kernel(const int* __restrict__ ei, int E) {
    int i = blockIdx.x * blockDim.x + threadIdx.x;
    if (i < E) {
        int dst = ei[E + i];
        int pos = atomicAdd(&g_cursor[dst], 1);
        g_csr[pos] = ei[i];
    }
}

// ------------------- Gather-mean: warp per content node --------------------
__global__ void agg_kernel(int nc) {
    const int warp = (blockIdx.x * blockDim.x + threadIdx.x) >> 5;
    const int lane = threadIdx.x & 31;
    if (warp >= nc) return;
    const int s0 = g_off[warp];
    const int d = g_deg[warp];
    float4 acc = make_float4(0.f, 0.f, 0.f, 0.f);
    for (int base = 0; base < d; base += 32) {
        int my = (base + lane < d) ? g_csr[s0 + base + lane] : 0;
        int lim = min(32, d - base);
        for (int j = 0; j < lim; j++) {
            int nbr = __shfl_sync(0xffffffffu, my, j);
            float4 v = reinterpret_cast<const float4*>(g_hu + (size_t)nbr * H)[lane];
            acc.x += v.x; acc.y += v.y; acc.z += v.z; acc.w += v.w;
        }
    }
    float inv = 1.f / fmaxf((float)d, 1.f);
    acc.x *= inv; acc.y *= inv; acc.z *= inv; acc.w *= inv;
    reinterpret_cast<float4*>(g_mean + (size_t)warp * H)[lane] = acc;
}

// ---------------------------------------------------------------------------
extern "C" void kernel_launch(void* const* d_in, const int* in_sizes, int n_in,
                              void* d_out, int out_size) {
    const float* x_content = (const float*)d_in[0];
    const float* x_user    = (const float*)d_in[1];
    const int*   ei        = (const int*)d_in[2];   // int32 (JAX x64 off)
    const float* Wc = (const float*)d_in[3];
    const float* bc = (const float*)d_in[4];
    const float* Wu = (const float*)d_in[5];
    const float* bu = (const float*)d_in[6];
    const float* Wl = (const float*)d_in[7];
    const float* bl = (const float*)d_in[8];
    const float* Wr = (const float*)d_in[9];
    const float* Wo = (const float*)d_in[10];
    const float* bo = (const float*)d_in[11];
    float* out = (float*)d_out;

    const int Nc = in_sizes[0] / 256;
    const int Nu = in_sizes[1] / 128;
    const int E  = in_sizes[2] / 2;

    // proj (content): B 2*256*136*2 + A double 2*(2*64*136*2) = 208896
    const int smem_proj = (2 * 256 * 136 + 2 * (2 * 64 * 136)) * 2;
    // combine (round 7): 210944
    const int smem_comb = (2 * 256 * 136 + 2 * 64 * 136 + 2 * 128 * 72) * 2;

    cudaFuncSetAttribute(proj_fused,
                         cudaFuncAttributeMaxDynamicSharedMemorySize, smem_proj);
    cudaFuncSetAttribute(combine_kernel,
                         cudaFuncAttributeMaxDynamicSharedMemorySize, smem_comb);

    // One-time stream/event setup (persists; no device memory involved)
    static cudaStream_t s1 = nullptr;
    static cudaEvent_t eFork = nullptr, eP = nullptr;
    if (s1 == nullptr) {
        cudaStreamCreateWithFlags(&s1, cudaStreamNonBlocking);
        cudaEventCreateWithFlags(&eFork, cudaEventDisableTiming);
        cudaEventCreateWithFlags(&eP, cudaEventDisableTiming);
    }

    const int nb = (Nc + 255) / 256;  // <= 512

    // Fork s1 from the (captured) default stream
    cudaEventRecord(eFork, 0);
    cudaStreamWaitEvent(s1, eFork, 0);

    // Default stream: CSR build (independent of projections)
    zero_deg_kernel<<<256, 256>>>(Nc);                       // #1
    hist_kernel<<<(E + 255) / 256, 256>>>(ei, E);            // #2
    scan1_kernel<<<nb, 256>>>(Nc);                           // #3

    // s1: fused projections (concurrent with CSR build)
    proj_fused<<<152, 256, smem_proj, s1>>>(x_content, x_user, Wc, bc, Wu, bu,
                                            Nc, Nu);         // #4 (profiled slot)
    cudaEventRecord(eP, s1);

    scan2_kernel<<<1, 512>>>(nb);                            // #5
    scan3_kernel<<<nb, 256>>>(Nc);
    fill_kernel<<<(E + 255) / 256, 256>>>(ei, E);

    // agg needs CSR (stream order) + g_hu (eP)
    cudaStreamWaitEvent(0, eP, 0);
    agg_kernel<<<(Nc * 32 + 255) / 256, 256>>>(Nc);

    // combine needs agg (stream order) + g_hc (eP, already joined)
    combine_kernel<<<152, 256, smem_comb>>>(Wl, bl, Wr, Wo, bo, out, Nc);
}

// round 15
// speedup vs baseline: 1.1003x; 1.0427x over previous
#include <cuda_runtime.h>
#include <cuda_bf16.h>
#include <stdint.h>

#define H      128
#define NC_MAX 100000
#define NU_MAX 100000
#define E_MAX  1600000

// Scratch: __device__ globals (allocation-free rule)
__device__ __align__(16) float g_hu[(size_t)NU_MAX * H];
__device__ __align__(16) float g_hc[(size_t)NC_MAX * H];
__device__ __align__(16) float g_mean[(size_t)NC_MAX * H];
__device__ int g_deg[NC_MAX];
__device__ int g_off[NC_MAX];
__device__ int g_cursor[NC_MAX];
__device__ int g_csr[E_MAX];
__device__ int g_bsum[512];

// ============================= PTX helpers (portable) =======================
__device__ __forceinline__ uint32_t smem_u32(const void* p) {
    uint32_t a;
    asm("{ .reg .u64 t; cvta.to.shared.u64 t, %1; cvt.u32.u64 %0, t; }"
        : "=r"(a) : "l"(p));
    return a;
}
__device__ __forceinline__ void ldsm_x4(uint32_t* r, uint32_t addr) {
    asm volatile("ldmatrix.sync.aligned.m8n8.x4.shared.b16 {%0,%1,%2,%3}, [%4];"
                 : "=r"(r[0]), "=r"(r[1]), "=r"(r[2]), "=r"(r[3]) : "r"(addr));
}
__device__ __forceinline__ void ldsm_x4_t(uint32_t* r, uint32_t addr) {
    asm volatile("ldmatrix.sync.aligned.m8n8.x4.trans.shared.b16 {%0,%1,%2,%3}, [%4];"
                 : "=r"(r[0]), "=r"(r[1]), "=r"(r[2]), "=r"(r[3]) : "r"(addr));
}
__device__ __forceinline__ void mma_bf16(float* d, const uint32_t* a,
                                         uint32_t b0, uint32_t b1) {
    asm volatile(
        "mma.sync.aligned.m16n8k16.row.col.f32.bf16.bf16.f32 "
        "{%0,%1,%2,%3}, {%4,%5,%6,%7}, {%8,%9}, {%0,%1,%2,%3};"
        : "+f"(d[0]), "+f"(d[1]), "+f"(d[2]), "+f"(d[3])
        : "r"(a[0]), "r"(a[1]), "r"(a[2]), "r"(a[3]), "r"(b0), "r"(b1));
}

// fp32 -> (bf16 hi, bf16 lo), packed
__device__ __forceinline__ void cvt_hl4(float4 v, uint2& hv, uint2& lv) {
    float f[4] = {v.x, v.y, v.z, v.w};
    uint32_t h[4], l[4];
#pragma unroll
    for (int j = 0; j < 4; j++) {
        __nv_bfloat16 hb = __float2bfloat16_rn(f[j]);
        float hf = __bfloat162float(hb);
        __nv_bfloat16 lb = __float2bfloat16_rn(f[j] - hf);
        h[j] = (uint32_t)__bfloat16_as_ushort(hb);
        l[j] = (uint32_t)__bfloat16_as_ushort(lb);
    }
    hv = make_uint2(h[0] | (h[1] << 16), h[2] | (h[3] << 16));
    lv = make_uint2(l[0] | (l[1] << 16), l[2] | (l[3] << 16));
}
__device__ __forceinline__ void cvt_hl2(float a, float b, uint32_t& hv, uint32_t& lv) {
    __nv_bfloat16 h0 = __float2bfloat16_rn(a), h1 = __float2bfloat16_rn(b);
    float f0 = __bfloat162float(h0), f1 = __bfloat162float(h1);
    __nv_bfloat16 l0 = __float2bfloat16_rn(a - f0), l1 = __float2bfloat16_rn(b - f1);
    hv = (uint32_t)__bfloat16_as_ushort(h0) |
         ((uint32_t)__bfloat16_as_ushort(h1) << 16);
    lv = (uint32_t)__bfloat16_as_ushort(l0) |
         ((uint32_t)__bfloat16_as_ushort(l1) << 16);
}

// ============================================================================
// Projection (PIPELINED, round-11 body): relu(X @ W + b) -> dst. 64-row
// tiles, 16x64 warp tiles, double-buffered A (hi/lo). Per chunk g: MMA(g)
// overlaps convert(g+1) (other parity) and LDG(g+2) (regs). One sync/chunk.
// ============================================================================
template <int KTOT>
__device__ void run_proj(const float* __restrict__ X, const float* __restrict__ W,
                         const float* __restrict__ bias, float* __restrict__ dst,
                         int N, int bid, int nb, char* smc) {
    constexpr int NCHUNK = KTOT / 128;
    constexpr int PITCH = 136;
    constexpr int ABUF = 2 * 64 * PITCH;  // bf16 elems per buffer (hi+lo)
    __nv_bfloat16* Bh = reinterpret_cast<__nv_bfloat16*>(smc);
    __nv_bfloat16* Bl = Bh + KTOT * PITCH;
    __nv_bfloat16* Abase = Bl + KTOT * PITCH;  // 2 buffers of ABUF

    const int t = threadIdx.x;
    const int wid = t >> 5, lane = t & 31;
    const int wm = wid >> 1, wn = wid & 1;

    // Stage weights hi/lo
    for (int i = t; i < KTOT * 32; i += 256) {
        int k = i >> 5, n4 = (i & 31) * 4;
        float4 w = *reinterpret_cast<const float4*>(W + (size_t)k * 128 + n4);
        uint2 hv, lv;
        cvt_hl4(w, hv, lv);
        *reinterpret_cast<uint2*>(Bh + k * PITCH + n4) = hv;
        *reinterpret_cast<uint2*>(Bl + k * PITCH + n4) = lv;
    }

    const uint32_t ab_u = smem_u32(Abase);
    const uint32_t bh_u = smem_u32(Bh), bl_u = smem_u32(Bl);
    const int a_row_l = lane & 15, a_col_l = (lane >> 4) * 8;
    const int b_k_l = (lane & 7) + ((lane >> 3) & 1) * 8;
    const int b_n_l = (lane >> 4) * 8;

    float2 bv[8];
#pragma unroll
    for (int n8 = 0; n8 < 8; n8++)
        bv[n8] = *reinterpret_cast<const float2*>(bias + wn * 64 + n8 * 8 +
                                                  (lane & 3) * 2);

    const int ntiles = (N + 63) >> 6;
    const int nloc = (ntiles > bid) ? (ntiles - 1 - bid) / nb + 1 : 0;
    const int total = nloc * NCHUNK;

    float4 vv[8];
    auto ldg_chunk = [&](int g) {
        const int tile = bid + (g / NCHUNK) * nb;
        const int c = g % NCHUNK;
        const int row0 = tile << 6;
#pragma unroll
        for (int it = 0; it < 8; it++) {
            int i = t + it * 256;
            int rr = row0 + (i >> 5), c4 = (i & 31) * 4;
            vv[it] = (rr < N) ? *reinterpret_cast<const float4*>(
                                    X + (size_t)rr * KTOT + c * 128 + c4)
                              : make_float4(0.f, 0.f, 0.f, 0.f);
        }
    };
    auto cvt_chunk = [&](int g) {
        __nv_bfloat16* Ah = Abase + (g & 1) * ABUF;
        __nv_bfloat16* Al = Ah + 64 * PITCH;
#pragma unroll
        for (int it = 0; it < 8; it++) {
            int i = t + it * 256;
            int r = i >> 5, c4 = (i & 31) * 4;
            uint2 hv, lv;
            cvt_hl4(vv[it], hv, lv);
            *reinterpret_cast<uint2*>(Ah + r * PITCH + c4) = hv;
            *reinterpret_cast<uint2*>(Al + r * PITCH + c4) = lv;
        }
    };

    if (total > 0) {
        ldg_chunk(0);
        cvt_chunk(0);
        if (total > 1) ldg_chunk(1);
    }
    __syncthreads();

    float acc[8][4];
#pragma unroll
    for (int n8 = 0; n8 < 8; n8++)
#pragma unroll
        for (int e = 0; e < 4; e++) acc[n8][e] = 0.f;

    for (int g = 0; g < total; g++) {
        const int tile = bid + (g / NCHUNK) * nb;
        const int c = g % NCHUNK;
        const uint32_t ah_u = ab_u + (uint32_t)(g & 1) * ABUF * 2;
        const uint32_t al_u = ah_u + 64 * PITCH * 2;

#pragma unroll 1
        for (int k0 = 0; k0 < 128; k0 += 16) {
            uint32_t afh[4], afl[4];
            uint32_t aoff = (uint32_t)((wm * 16 + a_row_l) * PITCH + k0 + a_col_l) * 2;
            ldsm_x4(afh, ah_u + aoff);
            ldsm_x4(afl, al_u + aoff);
            uint32_t bfh[4][4], bfl[4][4];
#pragma unroll
            for (int ng = 0; ng < 4; ng++) {
                uint32_t boff = (uint32_t)((c * 128 + k0 + b_k_l) * PITCH +
                                           wn * 64 + ng * 16 + b_n_l) * 2;
                ldsm_x4_t(bfh[ng], bh_u + boff);
                ldsm_x4_t(bfl[ng], bl_u + boff);
            }
#pragma unroll
            for (int n8 = 0; n8 < 8; n8++) {
                int ng = n8 >> 1, sb = (n8 & 1) * 2;
                mma_bf16(acc[n8], afh, bfh[ng][sb], bfh[ng][sb + 1]);
                mma_bf16(acc[n8], afh, bfl[ng][sb], bfl[ng][sb + 1]);
                mma_bf16(acc[n8], afl, bfh[ng][sb], bfh[ng][sb + 1]);
            }
        }

        if (g + 1 < total) cvt_chunk(g + 1);
        if (g + 2 < total) ldg_chunk(g + 2);

        if (c == NCHUNK - 1) {
            const int row0 = tile << 6;
            int r0w = row0 + wm * 16 + (lane >> 2);
#pragma unroll
            for (int n8 = 0; n8 < 8; n8++) {
                int col = wn * 64 + n8 * 8 + (lane & 3) * 2;
                float2 o0, o1;
                o0.x = fmaxf(acc[n8][0] + bv[n8].x, 0.f);
                o0.y = fmaxf(acc[n8][1] + bv[n8].y, 0.f);
                o1.x = fmaxf(acc[n8][2] + bv[n8].x, 0.f);
                o1.y = fmaxf(acc[n8][3] + bv[n8].y, 0.f);
                if (r0w < N)
                    *reinterpret_cast<float2*>(dst + (size_t)r0w * 128 + col) = o0;
                if (r0w + 8 < N)
                    *reinterpret_cast<float2*>(dst + (size_t)(r0w + 8) * 128 + col) = o1;
            }
#pragma unroll
            for (int n8 = 0; n8 < 8; n8++)
#pragma unroll
                for (int e = 0; e < 4; e++) acc[n8][e] = 0.f;
        }
        __syncthreads();
    }
}

// Split projection kernels (full 152-CTA grids each)
__global__ void __launch_bounds__(256, 1)
proj_user_kernel(const float* __restrict__ xu, const float* __restrict__ Wu,
                 const float* __restrict__ bu, int Nu) {
    extern __shared__ char smc[];
    run_proj<128>(xu, Wu, bu, g_hu, Nu, blockIdx.x, gridDim.x, smc);
}
__global__ void __launch_bounds__(256, 1)
proj_content_kernel(const float* __restrict__ xc, const float* __restrict__ Wc,
                    const float* __restrict__ bc, int Nc) {
    extern __shared__ char smc[];
    run_proj<256>(xc, Wc, bc, g_hc, Nc, blockIdx.x, gridDim.x, smc);
}

// ============================================================================
// Combine + output fused (round-7 version, unchanged from 329us best).
// ============================================================================
__global__ void __launch_bounds__(256, 1)
combine_kernel(const float* __restrict__ Wl, const float* __restrict__ bl,
               const float* __restrict__ Wr, const float* __restrict__ Wo,
               const float* __restrict__ bo, float* __restrict__ out, int N) {
    constexpr int PITCH = 136, OPITCH = 72;
    extern __shared__ char smc[];
    __nv_bfloat16* Bh = reinterpret_cast<__nv_bfloat16*>(smc);
    __nv_bfloat16* Bl_ = Bh + 256 * PITCH;
    __nv_bfloat16* Ah = Bl_ + 256 * PITCH;
    __nv_bfloat16* Al = Ah + 64 * PITCH;
    __nv_bfloat16* Oh = Al + 64 * PITCH;
    __nv_bfloat16* Ol = Oh + 128 * OPITCH;

    const int t = threadIdx.x;
    const int wid = t >> 5, lane = t & 31;
    const int wm = wid >> 1, wn = wid & 1;

    for (int i = t; i < 256 * 32; i += 256) {
        int k = i >> 5, n4 = (i & 31) * 4;
        const float* wsrc = (k < 128) ? Wl + (size_t)k * 128
                                      : Wr + (size_t)(k - 128) * 128;
        float4 w = *reinterpret_cast<const float4*>(wsrc + n4);
        uint2 hv, lv;
        cvt_hl4(w, hv, lv);
        *reinterpret_cast<uint2*>(Bh + k * PITCH + n4) = hv;
        *reinterpret_cast<uint2*>(Bl_ + k * PITCH + n4) = lv;
    }
    for (int i = t; i < 128 * 16; i += 256) {
        int k = i >> 4, n4 = (i & 15) * 4;
        float4 w = *reinterpret_cast<const float4*>(Wo + (size_t)k * 64 + n4);
        uint2 hv, lv;
        cvt_hl4(w, hv, lv);
        *reinterpret_cast<uint2*>(Oh + k * OPITCH + n4) = hv;
        *reinterpret_cast<uint2*>(Ol + k * OPITCH + n4) = lv;
    }

    const uint32_t ah_u = smem_u32(Ah), al_u = smem_u32(Al);
    const uint32_t bh_u = smem_u32(Bh), bl_u = smem_u32(Bl_);
    const uint32_t oh_u = smem_u32(Oh), ol_u = smem_u32(Ol);
    const int a_row_l = lane & 15, a_col_l = (lane >> 4) * 8;
    const int b_k_l = (lane & 7) + ((lane >> 3) & 1) * 8;
    const int b_n_l = (lane >> 4) * 8;

    float2 blv[8];
#pragma unroll
    for (int n8 = 0; n8 < 8; n8++)
        blv[n8] = *reinterpret_cast<const float2*>(bl + wn * 64 + n8 * 8 +
                                                   (lane & 3) * 2);
    float2 bov[4];
#pragma unroll
    for (int n8 = 0; n8 < 4; n8++)
        bov[n8] = *reinterpret_cast<const float2*>(bo + wn * 32 + n8 * 8 +
                                                   (lane & 3) * 2);

    const int ntiles = (N + 63) >> 6;
    for (int tile = blockIdx.x; tile < ntiles; tile += gridDim.x) {
        const int row0 = tile << 6;
        float acc[8][4];
#pragma unroll
        for (int n8 = 0; n8 < 8; n8++)
#pragma unroll
            for (int e = 0; e < 4; e++) acc[n8][e] = 0.f;

        for (int c = 0; c < 2; ++c) {
            __syncthreads();
            const float* src = (c == 0) ? g_mean : g_hc;
            float4 vv[8];
#pragma unroll
            for (int it = 0; it < 8; it++) {
                int i = t + it * 256;
                int rr = row0 + (i >> 5), c4 = (i & 31) * 4;
                vv[it] = (rr < N) ? *reinterpret_cast<const float4*>(
                                        src + (size_t)rr * 128 + c4)
                                  : make_float4(0.f, 0.f, 0.f, 0.f);
            }
#pragma unroll
            for (int it = 0; it < 8; it++) {
                int i = t + it * 256;
                int r = i >> 5, c4 = (i & 31) * 4;
                uint2 hv, lv;
                cvt_hl4(vv[it], hv, lv);
                *reinterpret_cast<uint2*>(Ah + r * PITCH + c4) = hv;
                *reinterpret_cast<uint2*>(Al + r * PITCH + c4) = lv;
            }
            __syncthreads();
#pragma unroll 1
            for (int k0 = 0; k0 < 128; k0 += 16) {
                uint32_t afh[4], afl[4];
                uint32_t aoff = (uint32_t)((wm * 16 + a_row_l) * PITCH + k0 + a_col_l) * 2;
                ldsm_x4(afh, ah_u + aoff);
                ldsm_x4(afl, al_u + aoff);
                uint32_t bfh[4][4], bfl[4][4];
#pragma unroll
                for (int ng = 0; ng < 4; ng++) {
                    uint32_t boff = (uint32_t)((c * 128 + k0 + b_k_l) * PITCH +
                                               wn * 64 + ng * 16 + b_n_l) * 2;
                    ldsm_x4_t(bfh[ng], bh_u + boff);
                    ldsm_x4_t(bfl[ng], bl_u + boff);
                }
#pragma unroll
                for (int n8 = 0; n8 < 8; n8++) {
                    int ng = n8 >> 1, sb = (n8 & 1) * 2;
                    mma_bf16(acc[n8], afh, bfh[ng][sb], bfh[ng][sb + 1]);
                    mma_bf16(acc[n8], afh, bfl[ng][sb], bfl[ng][sb + 1]);
                    mma_bf16(acc[n8], afl, bfh[ng][sb], bfh[ng][sb + 1]);
                }
            }
        }
        __syncthreads();

        {
            int r1 = wm * 16 + (lane >> 2);
#pragma unroll
            for (int n8 = 0; n8 < 8; n8++) {
                int col = wn * 64 + n8 * 8 + (lane & 3) * 2;
                uint32_t hv, lv;
                cvt_hl2(acc[n8][0] + blv[n8].x, acc[n8][1] + blv[n8].y, hv, lv);
                *reinterpret_cast<uint32_t*>(Ah + r1 * PITCH + col) = hv;
                *reinterpret_cast<uint32_t*>(Al + r1 * PITCH + col) = lv;
                cvt_hl2(acc[n8][2] + blv[n8].x, acc[n8][3] + blv[n8].y, hv, lv);
                *reinterpret_cast<uint32_t*>(Ah + (r1 + 8) * PITCH + col) = hv;
                *reinterpret_cast<uint32_t*>(Al + (r1 + 8) * PITCH + col) = lv;
            }
        }
        __syncthreads();

        float acc2[4][4];
#pragma unroll
        for (int n8 = 0; n8 < 4; n8++)
#pragma unroll
            for (int e = 0; e < 4; e++) acc2[n8][e] = 0.f;
#pragma unroll 1
        for (int k0 = 0; k0 < 128; k0 += 16) {
            uint32_t afh[4], afl[4];
            uint32_t aoff = (uint32_t)((wm * 16 + a_row_l) * PITCH + k0 + a_col_l) * 2;
            ldsm_x4(afh, ah_u + aoff);
            ldsm_x4(afl, al_u + aoff);
            uint32_t bfh[2][4], bfl[2][4];
#pragma unroll
            for (int ng = 0; ng < 2; ng++) {
                uint32_t boff = (uint32_t)((k0 + b_k_l) * OPITCH +
                                           wn * 32 + ng * 16 + b_n_l) * 2;
                ldsm_x4_t(bfh[ng], oh_u + boff);
                ldsm_x4_t(bfl[ng], ol_u + boff);
            }
#pragma unroll
            for (int n8 = 0; n8 < 4; n8++) {
                int ng = n8 >> 1, sb = (n8 & 1) * 2;
                mma_bf16(acc2[n8], afh, bfh[ng][sb], bfh[ng][sb + 1]);
                mma_bf16(acc2[n8], afh, bfl[ng][sb], bfl[ng][sb + 1]);
                mma_bf16(acc2[n8], afl, bfh[ng][sb], bfh[ng][sb + 1]);
            }
        }
        int r0w = row0 + wm * 16 + (lane >> 2);
#pragma unroll
        for (int n8 = 0; n8 < 4; n8++) {
            int col = wn * 32 + n8 * 8 + (lane & 3) * 2;
            float2 o0, o1;
            o0.x = acc2[n8][0] + bov[n8].x;
            o0.y = acc2[n8][1] + bov[n8].y;
            o1.x = acc2[n8][2] + bov[n8].x;
            o1.y = acc2[n8][3] + bov[n8].y;
            if (r0w < N)
                *reinterpret_cast<float2*>(out + (size_t)r0w * 64 + col) = o0;
            if (r0w + 8 < N)
                *reinterpret_cast<float2*>(out + (size_t)(r0w + 8) * 64 + col) = o1;
        }
    }
}

// ============================ CSR build =====================================
__global__ void zero_deg_kernel(int nc) {
    int i = blockIdx.x * blockDim.x + threadIdx.x;
    int stride = gridDim.x * blockDim.x;
    for (; i < nc; i += stride) g_deg[i] = 0;
}
__global__ void hist_kernel(const int* __restrict__ ei, int E) {
    int i = blockIdx.x * blockDim.x + threadIdx.x;
    if (i < E) atomicAdd(&g_deg[ei[E + i]], 1);
}
__global__ void scan1_kernel(int nc) {
    __shared__ int s[256];
    int t = threadIdx.x;
    int i = blockIdx.x * 256 + t;
    s[t] = (i < nc) ? g_deg[i] : 0;
    __syncthreads();
    for (int d = 128; d > 0; d >>= 1) {
        if (t < d) s[t] += s[t + d];
        __syncthreads();
    }
    if (t == 0) g_bsum[blockIdx.x] = s[0];
}
__global__ void scan2_kernel(int nb) {
    __shared__ int s[512];
    int t = threadIdx.x;
    int v = (t < nb) ? g_bsum[t] : 0;
    s[t] = v;
    __syncthreads();
    for (int d = 1; d < 512; d <<= 1) {
        int add = (t >= d) ? s[t - d] : 0;
        __syncthreads();
        s[t] += add;
        __syncthreads();
    }
    if (t < nb) g_bsum[t] = s[t] - v;
}
__global__ void scan3_kernel(int nc) {
    __shared__ int s[256];
    int t = threadIdx.x;
    int i = blockIdx.x * 256 + t;
    int v = (i < nc) ? g_deg[i] : 0;
    s[t] = v;
    __syncthreads();
    for (int d = 1; d < 256; d <<= 1) {
        int add = (t >= d) ? s[t - d] : 0;
        __syncthreads();
        s[t] += add;
        __syncthreads();
    }
    if (i < nc) {
        int off = g_bsum[blockIdx.x] + s[t] - v;
        g_off[i] = off;
        g_cursor[i] = off;
    }
}
__global__ void fill_kernel(const int* __restrict__ ei, int E) {
    int i = blockIdx.x * blockDim.x + threadIdx.x;
    if (i < E) {
        int dst = ei[E + i];
        int pos = atomicAdd(&g_cursor[dst], 1);
        g_csr[pos] = ei[i];
    }
}

// ------------------- Gather-mean: warp per content node --------------------
__global__ void agg_kernel(int nc) {
    const int warp = (blockIdx.x * blockDim.x + threadIdx.x) >> 5;
    const int lane = threadIdx.x & 31;
    if (warp >= nc) return;
    const int s0 = g_off[warp];
    const int d = g_deg[warp];
    float4 acc = make_float4(0.f, 0.f, 0.f, 0.f);
    for (int base = 0; base < d; base += 32) {
        int my = (base + lane < d) ? g_csr[s0 + base + lane] : 0;
        int lim = min(32, d - base);
        for (int j = 0; j < lim; j++) {
            int nbr = __shfl_sync(0xffffffffu, my, j);
            float4 v = reinterpret_cast<const float4*>(g_hu + (size_t)nbr * H)[lane];
            acc.x += v.x; acc.y += v.y; acc.z += v.z; acc.w += v.w;
        }
    }
    float inv = 1.f / fmaxf((float)d, 1.f);
    acc.x *= inv; acc.y *= inv; acc.z *= inv; acc.w *= inv;
    reinterpret_cast<float4*>(g_mean + (size_t)warp * H)[lane] = acc;
}

// ---------------------------------------------------------------------------
extern "C" void kernel_launch(void* const* d_in, const int* in_sizes, int n_in,
                              void* d_out, int out_size) {
    const float* x_content = (const float*)d_in[0];
    const float* x_user    = (const float*)d_in[1];
    const int*   ei        = (const int*)d_in[2];   // int32 (JAX x64 off)
    const float* Wc = (const float*)d_in[3];
    const float* bc = (const float*)d_in[4];
    const float* Wu = (const float*)d_in[5];
    const float* bu = (const float*)d_in[6];
    const float* Wl = (const float*)d_in[7];
    const float* bl = (const float*)d_in[8];
    const float* Wr = (const float*)d_in[9];
    const float* Wo = (const float*)d_in[10];
    const float* bo = (const float*)d_in[11];
    float* out = (float*)d_out;

    const int Nc = in_sizes[0] / 256;
    const int Nu = in_sizes[1] / 128;
    const int E  = in_sizes[2] / 2;

    // proj user: B 2*128*136*2 + A 2*(2*64*136)*2 = 139264
    const int smem_pu = (2 * 128 * 136 + 2 * (2 * 64 * 136)) * 2;
    // proj content: B 2*256*136*2 + A double = 208896
    const int smem_pc = (2 * 256 * 136 + 2 * (2 * 64 * 136)) * 2;
    // combine: 210944
    const int smem_cb = (2 * 256 * 136 + 2 * 64 * 136 + 2 * 128 * 72) * 2;

    cudaFuncSetAttribute(proj_user_kernel,
                         cudaFuncAttributeMaxDynamicSharedMemorySize, smem_pu);
    cudaFuncSetAttribute(proj_content_kernel,
                         cudaFuncAttributeMaxDynamicSharedMemorySize, smem_pc);
    cudaFuncSetAttribute(combine_kernel,
                         cudaFuncAttributeMaxDynamicSharedMemorySize, smem_cb);

    // One-time stream/event setup (persists; no device memory involved)
    static cudaStream_t s1 = nullptr;
    static cudaEvent_t eFork = nullptr, eU = nullptr, eC = nullptr;
    if (s1 == nullptr) {
        cudaStreamCreateWithFlags(&s1, cudaStreamNonBlocking);
        cudaEventCreateWithFlags(&eFork, cudaEventDisableTiming);
        cudaEventCreateWithFlags(&eU, cudaEventDisableTiming);
        cudaEventCreateWithFlags(&eC, cudaEventDisableTiming);
    }

    const int nb = (Nc + 255) / 256;  // <= 512

    // Fork s1 from the (captured) default stream
    cudaEventRecord(eFork, 0);
    cudaStreamWaitEvent(s1, eFork, 0);

    // Default stream: CSR build (independent of projections)
    zero_deg_kernel<<<256, 256>>>(Nc);
    hist_kernel<<<(E + 255) / 256, 256>>>(ei, E);
    scan1_kernel<<<nb, 256>>>(Nc);

    // s1: projections (user first -> unblocks agg early)
    proj_user_kernel<<<152, 256, smem_pu, s1>>>(x_user, Wu, bu, Nu);
    cudaEventRecord(eU, s1);
    proj_content_kernel<<<152, 256, smem_pc, s1>>>(x_content, Wc, bc, Nc);
    cudaEventRecord(eC, s1);

    scan2_kernel<<<1, 512>>>(nb);
    scan3_kernel<<<nb, 256>>>(Nc);
    fill_kernel<<<(E + 255) / 256, 256>>>(ei, E);

    // agg: needs CSR (stream order) + g_hu (eU). Overlaps proj_content.
    cudaStreamWaitEvent(0, eU, 0);
    agg_kernel<<<(Nc * 32 + 255) / 256, 256>>>(Nc);

    // combine: needs agg (stream order) + g_hc (eC)
    cudaStreamWaitEvent(0, eC, 0);
    combine_kernel<<<152, 256, smem_cb>>>(Wl, bl, Wr, Wo, bo, out, Nc);
}